// round 2
// baseline (speedup 1.0000x reference)
#include <cuda_runtime.h>

// ---------------------------------------------------------------------------
// SFMCNN: 3 towers of (RBF-conv -> triangle -> crelu -> alpha-pool) x2 + conv
// then flatten + FC.  All fp32.  Scratch lives in __device__ globals.
// ---------------------------------------------------------------------------

#define NB   128   // batch
#define NT   3     // towers
#define NBT  (NB*NT)

// scratch buffers
__device__ float g_a1[NBT * 64 * 24 * 24];    // pooled layer1 output
__device__ float g_a2[NBT * 128 * 12 * 12];   // pooled layer2 output
__device__ float g_a3[NB * 110592];           // layer3 output, FC-ready layout
__device__ float g_xsq2[NBT * 24 * 24];
__device__ float g_xsq3[NBT * 12 * 12];
__device__ float g_wsq2[NT * 128];
__device__ float g_wsq3[NT * 256];

#define FC_SLABS 216
#define FC_SLAB_K 512                          // 216*512 = 110592
__device__ float g_part[FC_SLABS * NB * 100];

// ---------------------------------------------------------------------------
// prep: ||w||^2 for layers 2 and 3
// ---------------------------------------------------------------------------
__global__ void k_wsq(const float* __restrict__ W2, const float* __restrict__ W3) {
    int tid = blockIdx.x * blockDim.x + threadIdx.x;
    if (tid < NT * 128) {
        const float* p = W2 + tid * 576;
        float s = 0.f;
        for (int k = 0; k < 576; ++k) s += p[k] * p[k];
        g_wsq2[tid] = s;
    } else if (tid < NT * 128 + NT * 256) {
        int o = tid - NT * 128;
        const float* p = W3 + o * 1152;
        float s = 0.f;
        for (int k = 0; k < 1152; ++k) s += p[k] * p[k];
        g_wsq3[o] = s;
    }
}

// ---------------------------------------------------------------------------
// layer 1: RBF conv 5x5 (C=1 -> 64) on 48x48, pad 2 + triangle + crelu + pool
// one block per (b,t). 256 threads: 4 threads per output channel.
// ---------------------------------------------------------------------------
__global__ void __launch_bounds__(256) k_layer1(
    const float* __restrict__ x, const float* __restrict__ W1,
    const float* __restrict__ tri_w, const float* __restrict__ crelu_b,
    const float* __restrict__ sfm_alpha)
{
    __shared__ __align__(16) float xpad[52 * 52];
    __shared__ float xsqs[48 * 48];
    __shared__ float w1s[64 * 25];
    __shared__ float wsq1s[64];

    const int bt = blockIdx.x;
    const int t = bt % NT;
    const int tid = threadIdx.x;

    for (int idx = tid; idx < 52 * 52; idx += 256) xpad[idx] = 0.f;
    __syncthreads();
    for (int idx = tid; idx < 48 * 48; idx += 256) {
        int y = idx / 48, xx = idx % 48;
        xpad[(y + 2) * 52 + xx + 2] = x[bt * 2304 + idx];
    }
    for (int idx = tid; idx < 64 * 25; idx += 256) w1s[idx] = W1[t * 1600 + idx];
    __syncthreads();

    if (tid < 64) {
        float s = 0.f;
        #pragma unroll
        for (int k = 0; k < 25; ++k) { float w = w1s[tid * 25 + k]; s += w * w; }
        wsq1s[tid] = s;
    }
    // per-pixel window sum of squares (shared over all 64 channels)
    for (int idx = tid; idx < 48 * 48; idx += 256) {
        int y = idx / 48, xx = idx % 48;
        float s = 0.f;
        #pragma unroll
        for (int ky = 0; ky < 5; ++ky)
            #pragma unroll
            for (int kx = 0; kx < 5; ++kx) {
                float v = xpad[(y + ky) * 52 + xx + kx];
                s += v * v;
            }
        xsqs[idx] = s;
    }
    __syncthreads();

    const int o = tid >> 2, sub = tid & 3;
    float wr[25];
    #pragma unroll
    for (int k = 0; k < 25; ++k) wr[k] = w1s[o * 25 + k];
    const float wq = wsq1s[o];
    const float tw = tri_w[t * 3 + 0], inv_tw = 1.f / tw;
    const float cb = crelu_b[t * 3 + 0];
    const float al = sfm_alpha[t * 2 + 0];
    const float c00 = al * al * al * 0.25f, c01 = al * al * 0.25f;
    const float c10 = al * 0.25f, c11 = 0.25f;

    for (int it = 0; it < 144; ++it) {
        int p = it * 4 + sub;
        int i = p / 24, j = p % 24;
        float pt[6][6];
        #pragma unroll
        for (int r = 0; r < 6; ++r) {
            const float* row = &xpad[(2 * i + r) * 52 + 2 * j];
            #pragma unroll
            for (int s2 = 0; s2 < 3; ++s2) {
                float2 u = *(const float2*)(row + 2 * s2);
                pt[r][2 * s2] = u.x; pt[r][2 * s2 + 1] = u.y;
            }
        }
        float vv[2][2];
        #pragma unroll
        for (int a = 0; a < 2; ++a)
            #pragma unroll
            for (int b2 = 0; b2 < 2; ++b2) {
                float cr = 0.f;
                #pragma unroll
                for (int ky = 0; ky < 5; ++ky)
                    #pragma unroll
                    for (int kx = 0; kx < 5; ++kx)
                        cr += wr[ky * 5 + kx] * pt[a + ky][b2 + kx];
                float d = xsqs[(2 * i + a) * 48 + 2 * j + b2] - 2.f * cr + wq;
                d = fmaxf(d, 0.f);
                float v = 1.f - fminf(d, tw) * inv_tw;
                vv[a][b2] = (v >= cb) ? v : 0.f;
            }
        g_a1[(bt * 64 + o) * 576 + p] =
            c00 * vv[0][0] + c01 * vv[0][1] + c10 * vv[1][0] + c11 * vv[1][1];
    }
}

// ---------------------------------------------------------------------------
// xsq maps for layers 2 / 3: window(3x3, zero-pad) of sum_c a^2
// ---------------------------------------------------------------------------
__global__ void k_xsq2() {
    __shared__ float s[576];
    const int bt = blockIdx.x, tid = threadIdx.x;
    for (int p = tid; p < 576; p += 256) {
        float acc = 0.f;
        for (int c = 0; c < 64; ++c) {
            float v = g_a1[(bt * 64 + c) * 576 + p];
            acc += v * v;
        }
        s[p] = acc;
    }
    __syncthreads();
    for (int p = tid; p < 576; p += 256) {
        int y = p / 24, xx = p % 24;
        float acc = 0.f;
        #pragma unroll
        for (int dy = -1; dy <= 1; ++dy)
            #pragma unroll
            for (int dx = -1; dx <= 1; ++dx) {
                int yy = y + dy, xc = xx + dx;
                if (yy >= 0 && yy < 24 && xc >= 0 && xc < 24) acc += s[yy * 24 + xc];
            }
        g_xsq2[bt * 576 + p] = acc;
    }
}

__global__ void k_xsq3() {
    __shared__ float s[144];
    const int bt = blockIdx.x, tid = threadIdx.x;
    if (tid < 144) {
        float acc = 0.f;
        for (int c = 0; c < 128; ++c) {
            float v = g_a2[(bt * 128 + c) * 144 + tid];
            acc += v * v;
        }
        s[tid] = acc;
    }
    __syncthreads();
    if (tid < 144) {
        int y = tid / 12, xx = tid % 12;
        float acc = 0.f;
        #pragma unroll
        for (int dy = -1; dy <= 1; ++dy)
            #pragma unroll
            for (int dx = -1; dx <= 1; ++dx) {
                int yy = y + dy, xc = xx + dx;
                if (yy >= 0 && yy < 12 && xc >= 0 && xc < 12) acc += s[yy * 12 + xc];
            }
        g_xsq3[bt * 144 + tid] = acc;
    }
}

// ---------------------------------------------------------------------------
// layer 2: RBF conv 3x3 (64 -> 128) on 24x24, pad 1 + tri/crelu + pool
// grid (NBT, 8): 16 out channels per block.  288 threads: thread = (oc8, pooled
// position); 8 channels x 2x2 conv quad per thread -> 32 accumulators.
// ---------------------------------------------------------------------------
__global__ void __launch_bounds__(288) k_layer2(
    const float* __restrict__ W2, const float* __restrict__ tri_w,
    const float* __restrict__ crelu_b, const float* __restrict__ sfm_alpha)
{
    __shared__ __align__(16) float inPad[8 * 26 * 26];
    __shared__ __align__(16) float w_s[16 * 8 * 12];   // taps padded 9 -> 12

    const int bt = blockIdx.x, t = bt % NT;
    const int oBase = blockIdx.y * 16;
    const int tid = threadIdx.x;
    const int oc8 = tid / 144, pp = tid % 144;
    const int i = pp / 12, j = pp % 12;

    for (int idx = tid; idx < 8 * 676; idx += 288) inPad[idx] = 0.f;

    float acc[8][4];
    #pragma unroll
    for (int ol = 0; ol < 8; ++ol)
        #pragma unroll
        for (int q = 0; q < 4; ++q) acc[ol][q] = 0.f;

    for (int cc = 0; cc < 8; ++cc) {
        __syncthreads();
        for (int idx = tid; idx < 8 * 576; idx += 288) {
            int c = idx / 576, p = idx % 576, y = p / 24, xx = p % 24;
            inPad[c * 676 + (y + 1) * 26 + xx + 1] =
                g_a1[(bt * 64 + cc * 8 + c) * 576 + p];
        }
        for (int idx = tid; idx < 16 * 72; idx += 288) {
            int ol = idx / 72, r = idx % 72, c = r / 9, tap = r % 9;
            w_s[(ol * 8 + c) * 12 + tap] =
                W2[(t * 128 + oBase + ol) * 576 + (cc * 8 + c) * 9 + tap];
        }
        __syncthreads();

        #pragma unroll
        for (int c = 0; c < 8; ++c) {
            float pt[4][4];
            #pragma unroll
            for (int r = 0; r < 4; ++r) {
                const float* row = &inPad[c * 676 + (2 * i + r) * 26 + 2 * j];
                float2 u = *(const float2*)row;
                float2 v = *(const float2*)(row + 2);
                pt[r][0] = u.x; pt[r][1] = u.y; pt[r][2] = v.x; pt[r][3] = v.y;
            }
            #pragma unroll
            for (int ol = 0; ol < 8; ++ol) {
                const float* wp = &w_s[((oc8 * 8 + ol) * 8 + c) * 12];
                float4 w0 = *(const float4*)wp;
                float4 w1 = *(const float4*)(wp + 4);
                float w8 = wp[8];
                #pragma unroll
                for (int a = 0; a < 2; ++a)
                    #pragma unroll
                    for (int b2 = 0; b2 < 2; ++b2) {
                        float s = acc[ol][a * 2 + b2];
                        s += w0.x * pt[a][b2];
                        s += w0.y * pt[a][b2 + 1];
                        s += w0.z * pt[a][b2 + 2];
                        s += w0.w * pt[a + 1][b2];
                        s += w1.x * pt[a + 1][b2 + 1];
                        s += w1.y * pt[a + 1][b2 + 2];
                        s += w1.z * pt[a + 2][b2];
                        s += w1.w * pt[a + 2][b2 + 1];
                        s += w8  * pt[a + 2][b2 + 2];
                        acc[ol][a * 2 + b2] = s;
                    }
            }
        }
    }

    const float tw = tri_w[t * 3 + 1], inv_tw = 1.f / tw;
    const float cb = crelu_b[t * 3 + 1];
    const float al = sfm_alpha[t * 2 + 1];
    const float c00 = al * al * al * 0.25f, c01 = al * al * 0.25f;
    const float c10 = al * 0.25f, c11 = 0.25f;

    float xs[4];
    #pragma unroll
    for (int a = 0; a < 2; ++a)
        #pragma unroll
        for (int b2 = 0; b2 < 2; ++b2)
            xs[a * 2 + b2] = g_xsq2[bt * 576 + (2 * i + a) * 24 + 2 * j + b2];

    #pragma unroll
    for (int ol = 0; ol < 8; ++ol) {
        int og = oBase + oc8 * 8 + ol;
        float wq = g_wsq2[t * 128 + og];
        float vv[4];
        #pragma unroll
        for (int q = 0; q < 4; ++q) {
            float d = fmaxf(xs[q] - 2.f * acc[ol][q] + wq, 0.f);
            float v = 1.f - fminf(d, tw) * inv_tw;
            vv[q] = (v >= cb) ? v : 0.f;
        }
        g_a2[(bt * 128 + og) * 144 + i * 12 + j] =
            c00 * vv[0] + c01 * vv[1] + c10 * vv[2] + c11 * vv[3];
    }
}

// ---------------------------------------------------------------------------
// layer 3: RBF conv 3x3 (128 -> 256) on 12x12, pad 1 + tri/crelu (no pool)
// grid (NBT, 4): 64 out channels per block.  288 threads = 8 oc-groups x 36
// 2x2 quads.
// ---------------------------------------------------------------------------
__global__ void __launch_bounds__(288) k_layer3(
    const float* __restrict__ W3, const float* __restrict__ tri_w,
    const float* __restrict__ crelu_b)
{
    __shared__ __align__(16) float inPad[8 * 14 * 14];
    __shared__ __align__(16) float w_s[64 * 8 * 12];

    const int bt = blockIdx.x, t = bt % NT, b = bt / NT;
    const int oBase = blockIdx.y * 64;
    const int tid = threadIdx.x;
    const int oc8 = tid / 36, qq = tid % 36;
    const int i = qq / 6, j = qq % 6;

    for (int idx = tid; idx < 8 * 196; idx += 288) inPad[idx] = 0.f;

    float acc[8][4];
    #pragma unroll
    for (int ol = 0; ol < 8; ++ol)
        #pragma unroll
        for (int q = 0; q < 4; ++q) acc[ol][q] = 0.f;

    for (int cc = 0; cc < 16; ++cc) {
        __syncthreads();
        for (int idx = tid; idx < 8 * 144; idx += 288) {
            int c = idx / 144, p = idx % 144, y = p / 12, xx = p % 12;
            inPad[c * 196 + (y + 1) * 14 + xx + 1] =
                g_a2[(bt * 128 + cc * 8 + c) * 144 + p];
        }
        for (int idx = tid; idx < 64 * 72; idx += 288) {
            int ol = idx / 72, r = idx % 72, c = r / 9, tap = r % 9;
            w_s[(ol * 8 + c) * 12 + tap] =
                W3[(t * 256 + oBase + ol) * 1152 + (cc * 8 + c) * 9 + tap];
        }
        __syncthreads();

        #pragma unroll
        for (int c = 0; c < 8; ++c) {
            float pt[4][4];
            #pragma unroll
            for (int r = 0; r < 4; ++r) {
                const float* row = &inPad[c * 196 + (2 * i + r) * 14 + 2 * j];
                float2 u = *(const float2*)row;
                float2 v = *(const float2*)(row + 2);
                pt[r][0] = u.x; pt[r][1] = u.y; pt[r][2] = v.x; pt[r][3] = v.y;
            }
            #pragma unroll
            for (int ol = 0; ol < 8; ++ol) {
                const float* wp = &w_s[((oc8 * 8 + ol) * 8 + c) * 12];
                float4 w0 = *(const float4*)wp;
                float4 w1 = *(const float4*)(wp + 4);
                float w8 = wp[8];
                #pragma unroll
                for (int a = 0; a < 2; ++a)
                    #pragma unroll
                    for (int b2 = 0; b2 < 2; ++b2) {
                        float s = acc[ol][a * 2 + b2];
                        s += w0.x * pt[a][b2];
                        s += w0.y * pt[a][b2 + 1];
                        s += w0.z * pt[a][b2 + 2];
                        s += w0.w * pt[a + 1][b2];
                        s += w1.x * pt[a + 1][b2 + 1];
                        s += w1.y * pt[a + 1][b2 + 2];
                        s += w1.z * pt[a + 2][b2];
                        s += w1.w * pt[a + 2][b2 + 1];
                        s += w8  * pt[a + 2][b2 + 2];
                        acc[ol][a * 2 + b2] = s;
                    }
            }
        }
    }

    const float tw = tri_w[t * 3 + 2], inv_tw = 1.f / tw;
    const float cb = crelu_b[t * 3 + 2];

    #pragma unroll
    for (int ol = 0; ol < 8; ++ol) {
        int og = oBase + oc8 * 8 + ol;
        float wq = g_wsq3[t * 256 + og];
        #pragma unroll
        for (int a = 0; a < 2; ++a)
            #pragma unroll
            for (int b2 = 0; b2 < 2; ++b2) {
                int y = 2 * i + a, xx = 2 * j + b2;
                float d = fmaxf(g_xsq3[bt * 144 + y * 12 + xx]
                                - 2.f * acc[ol][a * 2 + b2] + wq, 0.f);
                float v = 1.f - fminf(d, tw) * inv_tw;
                v = (v >= cb) ? v : 0.f;
                g_a3[b * 110592 + t * 36864 + og * 144 + y * 12 + xx] = v;
            }
    }
}

// ---------------------------------------------------------------------------
// FC: out[b,n] = sum_k a3[b,k] * fcw[n,k] + fcb[n]
// split-K into 216 slabs of 512, deterministic two-stage reduction.
// ---------------------------------------------------------------------------
__global__ void __launch_bounds__(320) k_fc_partial(const float* __restrict__ fcw) {
    __shared__ __align__(16) float w_s[100 * 32];
    __shared__ __align__(16) float a_s[128 * 34];

    const int blk = blockIdx.x, tid = threadIdx.x;
    const int k0 = blk * FC_SLAB_K;
    const int ng = tid / 16, bq = tid % 16;   // ng in [0,20), bq in [0,16)
    const int n0 = ng * 5;

    float acc[5][8];
    #pragma unroll
    for (int qn = 0; qn < 5; ++qn)
        #pragma unroll
        for (int r = 0; r < 8; ++r) acc[qn][r] = 0.f;

    for (int ch = 0; ch < 16; ++ch) {
        int kb = k0 + ch * 32;
        __syncthreads();
        for (int idx = tid; idx < 100 * 32; idx += 320)
            w_s[idx] = fcw[(idx >> 5) * 110592 + kb + (idx & 31)];
        for (int idx = tid; idx < 128 * 32; idx += 320) {
            int bb = idx >> 5, kk = idx & 31;
            a_s[bb * 34 + kk] = g_a3[bb * 110592 + kb + kk];
        }
        __syncthreads();
        #pragma unroll 4
        for (int kk = 0; kk < 32; kk += 2) {
            float2 av[8];
            #pragma unroll
            for (int r = 0; r < 8; ++r)
                av[r] = *(const float2*)&a_s[(bq + 16 * r) * 34 + kk];
            #pragma unroll
            for (int qn = 0; qn < 5; ++qn) {
                float2 wv = *(const float2*)&w_s[(n0 + qn) * 32 + kk];
                #pragma unroll
                for (int r = 0; r < 8; ++r)
                    acc[qn][r] += wv.x * av[r].x + wv.y * av[r].y;
            }
        }
    }
    #pragma unroll
    for (int qn = 0; qn < 5; ++qn)
        #pragma unroll
        for (int r = 0; r < 8; ++r)
            g_part[blk * 12800 + (bq + 16 * r) * 100 + n0 + qn] = acc[qn][r];
}

__global__ void k_fc_reduce(const float* __restrict__ fcb, float* __restrict__ out) {
    int idx = blockIdx.x * blockDim.x + threadIdx.x;
    if (idx >= NB * 100) return;
    int n = idx % 100;
    float s = fcb[n];
    for (int sb = 0; sb < FC_SLABS; ++sb) s += g_part[sb * 12800 + idx];
    out[idx] = s;
}

// ---------------------------------------------------------------------------
extern "C" void kernel_launch(void* const* d_in, const int* in_sizes, int n_in,
                              void* d_out, int out_size) {
    const float* x         = (const float*)d_in[0];
    const float* W1        = (const float*)d_in[1];
    const float* W2        = (const float*)d_in[2];
    const float* W3        = (const float*)d_in[3];
    const float* tri_w     = (const float*)d_in[4];
    const float* crelu_b   = (const float*)d_in[5];
    const float* sfm_alpha = (const float*)d_in[6];
    const float* fcw       = (const float*)d_in[7];
    const float* fcb       = (const float*)d_in[8];
    float* out = (float*)d_out;

    k_wsq<<<5, 256>>>(W2, W3);
    k_layer1<<<NBT, 256>>>(x, W1, tri_w, crelu_b, sfm_alpha);
    k_xsq2<<<NBT, 256>>>();
    k_layer2<<<dim3(NBT, 8), 288>>>(W2, tri_w, crelu_b, sfm_alpha);
    k_xsq3<<<NBT, 256>>>();
    k_layer3<<<dim3(NBT, 4), 288>>>(W3, tri_w, crelu_b);
    k_fc_partial<<<FC_SLABS, 320>>>(fcw);
    k_fc_reduce<<<(NB * 100 + 255) / 256, 256>>>(fcb, out);
}

// round 4
// speedup vs baseline: 2.9161x; 2.9161x over previous
#include <cuda_runtime.h>
#include <cuda_fp16.h>
#include <cstdint>

#define NB 128
#define NT 3
#define NBT (NB*NT)

// ---------------- scratch ----------------
// a1: fp16 channel-last, padded 26 rows x 32 cols, 64 ch  (cell = (y+1)*32 + x+1)
__device__ __align__(16) __half g_a1f[NBT * 832 * 64];
// a2: fp16 channel-last, padded 14 rows x 16 cols, 128 ch (cell = (y+1)*16 + x+1)
__device__ __align__(16) __half g_a2f[NBT * 224 * 128];
__device__ float g_a3[NB * 110592];
__device__ float g_xsq2[NBT * 576];
__device__ float g_xsq3[NBT * 144];
__device__ float g_wsq2[NT * 128];       // from fp16-rounded weights
__device__ float g_wsq3[NT * 256];
// pre-swizzled fp16 weight images: W2 [t][tap]: 128oc x 64k (16KB);
// W3 [t][half][tap]: 2 k-planes x 128oc x 64k (32KB)
__device__ __align__(16) __half g_w2f[27 * 8192];
__device__ __align__(16) __half g_w3f[54 * 16384];

#define FC_SLABS 216
#define FC_SLAB_K 512
__device__ float g_part[FC_SLABS * NB * 100];

// ---------------- helpers ----------------
static __device__ __forceinline__ uint32_t smem_u32(const void* p) {
    uint32_t a;
    asm("{ .reg .u64 t; cvta.to.shared.u64 t, %1; cvt.u32.u64 %0, t; }" : "=r"(a) : "l"(p));
    return a;
}
static __device__ __forceinline__ uint32_t sw128(uint32_t off) {
    return off ^ ((off >> 3) & 0x70);
}
static __device__ __forceinline__ void ldsm_x4(uint32_t* r, uint32_t addr) {
    asm volatile("ldmatrix.sync.aligned.m8n8.x4.shared.b16 {%0,%1,%2,%3}, [%4];"
                 : "=r"(r[0]), "=r"(r[1]), "=r"(r[2]), "=r"(r[3]) : "r"(addr));
}
static __device__ __forceinline__ void ldsm_x2(uint32_t* r, uint32_t addr) {
    asm volatile("ldmatrix.sync.aligned.m8n8.x2.shared.b16 {%0,%1}, [%2];"
                 : "=r"(r[0]), "=r"(r[1]) : "r"(addr));
}
static __device__ __forceinline__ void mma16816(float* d, const uint32_t* a, const uint32_t* b) {
    asm volatile("mma.sync.aligned.m16n8k16.row.col.f32.f16.f16.f32 "
                 "{%0,%1,%2,%3}, {%4,%5,%6,%7}, {%8,%9}, {%0,%1,%2,%3};"
                 : "+f"(d[0]), "+f"(d[1]), "+f"(d[2]), "+f"(d[3])
                 : "r"(a[0]), "r"(a[1]), "r"(a[2]), "r"(a[3]), "r"(b[0]), "r"(b[1]));
}

// ---------------- zero padded activation buffers ----------------
__global__ void k_zero() {
    size_t i = (size_t)blockIdx.x * 256 + threadIdx.x;
    const size_t n1 = sizeof(g_a1f) / 16, n2 = sizeof(g_a2f) / 16;
    uint4 z = {0u, 0u, 0u, 0u};
    if (i < n1) ((uint4*)g_a1f)[i] = z;
    else if (i < n1 + n2) ((uint4*)g_a2f)[i - n1] = z;
}

// ---------------- prep: swizzled fp16 weight images + wsq ----------------
__global__ void k_prep(const float* __restrict__ W2, const float* __restrict__ W3) {
    int e = blockIdx.x * blockDim.x + threadIdx.x;
    if (e < 221184) {                         // t, tap, oc(128), k(64)
        int k = e & 63, oc = (e >> 6) & 127;
        int tap = (e >> 13) % 9, t = e / (9 * 8192);
        float w = W2[(t * 128 + oc) * 576 + k * 9 + tap];
        uint32_t sw = sw128((uint32_t)(oc * 128 + k * 2));
        *(__half*)((char*)(g_w2f + (size_t)(t * 9 + tap) * 8192) + sw) = __float2half(w);
    } else if (e < 221184 + 884736) {         // t, half, tap, oc(128), k(128)
        int e2 = e - 221184;
        int k = e2 & 127, oc = (e2 >> 7) & 127;
        int tap = (e2 >> 14) % 9, th = e2 / (9 * 16384);
        int t = th >> 1, half = th & 1;
        float w = W3[(t * 256 + half * 128 + oc) * 1152 + k * 9 + tap];
        uint32_t off = (uint32_t)((k >> 6) * 16384) + sw128((uint32_t)(oc * 128 + (k & 63) * 2));
        *(__half*)((char*)(g_w3f + (size_t)((th * 9 + tap)) * 16384) + off) = __float2half(w);
    }
}

__global__ void k_wsq(const float* __restrict__ W2, const float* __restrict__ W3) {
    int tid = blockIdx.x * blockDim.x + threadIdx.x;
    if (tid < NT * 128) {
        const float* p = W2 + tid * 576;
        float s = 0.f;
        for (int k = 0; k < 576; ++k) { float w = __half2float(__float2half(p[k])); s += w * w; }
        g_wsq2[tid] = s;
    } else if (tid < NT * 128 + NT * 256) {
        int o = tid - NT * 128;
        const float* p = W3 + o * 1152;
        float s = 0.f;
        for (int k = 0; k < 1152; ++k) { float w = __half2float(__float2half(p[k])); s += w * w; }
        g_wsq3[o] = s;
    }
}

// ---------------- layer 1: fp32 SIMT (proven) -> fp16 channel-last ----------------
__global__ void __launch_bounds__(256) k_layer1(
    const float* __restrict__ x, const float* __restrict__ W1,
    const float* __restrict__ tri_w, const float* __restrict__ crelu_b,
    const float* __restrict__ sfm_alpha)
{
    __shared__ __align__(16) float xpad[52 * 52];
    __shared__ float xsqs[48 * 48];
    __shared__ float w1s[64 * 25];
    __shared__ float wsq1s[64];

    const int bt = blockIdx.x, t = bt % NT, tid = threadIdx.x;

    for (int idx = tid; idx < 52 * 52; idx += 256) xpad[idx] = 0.f;
    __syncthreads();
    for (int idx = tid; idx < 48 * 48; idx += 256) {
        int y = idx / 48, xx = idx % 48;
        xpad[(y + 2) * 52 + xx + 2] = x[bt * 2304 + idx];
    }
    for (int idx = tid; idx < 64 * 25; idx += 256) w1s[idx] = W1[t * 1600 + idx];
    __syncthreads();

    if (tid < 64) {
        float s = 0.f;
        #pragma unroll
        for (int k = 0; k < 25; ++k) { float w = w1s[tid * 25 + k]; s += w * w; }
        wsq1s[tid] = s;
    }
    for (int idx = tid; idx < 48 * 48; idx += 256) {
        int y = idx / 48, xx = idx % 48;
        float s = 0.f;
        #pragma unroll
        for (int ky = 0; ky < 5; ++ky)
            #pragma unroll
            for (int kx = 0; kx < 5; ++kx) {
                float v = xpad[(y + ky) * 52 + xx + kx];
                s += v * v;
            }
        xsqs[idx] = s;
    }
    __syncthreads();

    const int o = tid >> 2, sub = tid & 3;
    float wr[25];
    #pragma unroll
    for (int k = 0; k < 25; ++k) wr[k] = w1s[o * 25 + k];
    const float wq = wsq1s[o];
    const float tw = tri_w[t * 3 + 0], inv_tw = 1.f / tw;
    const float cb = crelu_b[t * 3 + 0];
    const float al = sfm_alpha[t * 2 + 0];
    const float c00 = al * al * al * 0.25f, c01 = al * al * 0.25f;
    const float c10 = al * 0.25f, c11 = 0.25f;

    for (int it = 0; it < 144; ++it) {
        int p = it * 4 + sub;
        int i = p / 24, j = p % 24;
        float pt[6][6];
        #pragma unroll
        for (int r = 0; r < 6; ++r) {
            const float* row = &xpad[(2 * i + r) * 52 + 2 * j];
            #pragma unroll
            for (int s2 = 0; s2 < 3; ++s2) {
                float2 u = *(const float2*)(row + 2 * s2);
                pt[r][2 * s2] = u.x; pt[r][2 * s2 + 1] = u.y;
            }
        }
        float vv[2][2];
        #pragma unroll
        for (int a = 0; a < 2; ++a)
            #pragma unroll
            for (int b2 = 0; b2 < 2; ++b2) {
                float cr = 0.f;
                #pragma unroll
                for (int ky = 0; ky < 5; ++ky)
                    #pragma unroll
                    for (int kx = 0; kx < 5; ++kx)
                        cr += wr[ky * 5 + kx] * pt[a + ky][b2 + kx];
                float d = xsqs[(2 * i + a) * 48 + 2 * j + b2] - 2.f * cr + wq;
                d = fmaxf(d, 0.f);
                float v = 1.f - fminf(d, tw) * inv_tw;
                vv[a][b2] = (v >= cb) ? v : 0.f;
            }
        float pooled = c00 * vv[0][0] + c01 * vv[0][1] + c10 * vv[1][0] + c11 * vv[1][1];
        g_a1f[((size_t)bt * 832 + (i + 1) * 32 + (j + 1)) * 64 + o] = __float2half(pooled);
    }
}

// ---------------- xsq maps (from fp16 activations) ----------------
__global__ void __launch_bounds__(256) k_xsq2() {
    __shared__ float spad[26 * 26];
    const int bt = blockIdx.x, tid = threadIdx.x;
    for (int i = tid; i < 676; i += 256) spad[i] = 0.f;
    __syncthreads();
    for (int p = tid; p < 576; p += 256) {
        int y = p / 24, x = p % 24;
        const __half2* hp = (const __half2*)(g_a1f + ((size_t)bt * 832 + (y + 1) * 32 + x + 1) * 64);
        float acc = 0.f;
        #pragma unroll
        for (int c = 0; c < 32; ++c) {
            float2 f = __half22float2(hp[c]);
            acc += f.x * f.x + f.y * f.y;
        }
        spad[(y + 1) * 26 + (x + 1)] = acc;
    }
    __syncthreads();
    for (int p = tid; p < 576; p += 256) {
        int y = p / 24, x = p % 24;
        float acc = 0.f;
        #pragma unroll
        for (int r = 0; r < 3; ++r)
            #pragma unroll
            for (int cx = 0; cx < 3; ++cx)
                acc += spad[(y + r) * 26 + x + cx];
        g_xsq2[bt * 576 + p] = acc;
    }
}

__global__ void __launch_bounds__(256) k_xsq3() {
    __shared__ float spad[14 * 14];
    const int bt = blockIdx.x, tid = threadIdx.x;
    for (int i = tid; i < 196; i += 256) spad[i] = 0.f;
    __syncthreads();
    if (tid < 144) {
        int y = tid / 12, x = tid % 12;
        const __half2* hp = (const __half2*)(g_a2f + ((size_t)bt * 224 + (y + 1) * 16 + x + 1) * 128);
        float acc = 0.f;
        #pragma unroll
        for (int c = 0; c < 64; ++c) {
            float2 f = __half22float2(hp[c]);
            acc += f.x * f.x + f.y * f.y;
        }
        spad[(y + 1) * 14 + (x + 1)] = acc;
    }
    __syncthreads();
    if (tid < 144) {
        int y = tid / 12, x = tid % 12;
        float acc = 0.f;
        #pragma unroll
        for (int r = 0; r < 3; ++r)
            #pragma unroll
            for (int cx = 0; cx < 3; ++cx)
                acc += spad[(y + r) * 14 + x + cx];
        g_xsq3[bt * 144 + tid] = acc;
    }
}

// ---------------- conv2: implicit GEMM via mma.sync ----------------
// grid (NBT, 3): ytile of 8 conv rows.  512 thr = 16 warps (4M x 4N).
// M = 192 valid positions, N = 128 oc, K = 9 taps x 64 ch.
#define C2_AB 40960                 // A tile bytes (320 cells x 128B)
#define C2_DYN 99840                // max(A+W, vbuf 192*130*4)

__global__ void __launch_bounds__(512) k_conv2(
    const float* __restrict__ tri_w, const float* __restrict__ crelu_b,
    const float* __restrict__ sfm_alpha)
{
    extern __shared__ __align__(1024) unsigned char sm[];
    __shared__ uint32_t lutS[192];
    __shared__ float xsqS[192];
    __shared__ float wsqS[128];

    const int bt = blockIdx.x, t = bt % NT, ytile = blockIdx.y;
    const int y0 = ytile * 8;
    const int tid = threadIdx.x, wid = tid >> 5, lane = tid & 31;
    const uint32_t aBase = smem_u32(sm);
    const uint32_t wBase = aBase + C2_AB;

    // stage A: padded rows y0..y0+9 (320 cells), swizzled 16B chunks
    {
        const uint4* src = (const uint4*)(g_a1f + ((size_t)bt * 832 + y0 * 32) * 64);
        #pragma unroll
        for (int u = 0; u < 5; ++u) {
            int idx = tid + u * 512;
            uint32_t off = sw128((uint32_t)((idx >> 3) * 128 + (idx & 7) * 16));
            *(uint4*)(sm + off) = src[idx];
        }
    }
    if (tid < 192) {
        int r = tid / 24, c = tid % 24;
        lutS[tid] = (uint32_t)((r * 32 + c) * 128);
        xsqS[tid] = g_xsq2[bt * 576 + y0 * 24 + tid];
    }
    if (tid < 128) wsqS[tid] = g_wsq2[t * 128 + tid];

    const int wm = wid >> 2, wn = wid & 3;
    const int pBase = wm * 48, nBase = wn * 32;
    const int l15 = lane & 15;
    const uint32_t aKoff = ((lane >> 4) & 1) * 16;
    const uint32_t bRowK = (uint32_t)((nBase + (l15 & 7)) * 128 + ((l15 >> 3) & 1) * 16);

    float acc[3][4][4];
    #pragma unroll
    for (int mt = 0; mt < 3; ++mt)
        #pragma unroll
        for (int nt = 0; nt < 4; ++nt)
            #pragma unroll
            for (int e = 0; e < 4; ++e) acc[mt][nt][e] = 0.f;

    __syncthreads();
    uint32_t lutv[3];
    #pragma unroll
    for (int mt = 0; mt < 3; ++mt)
        lutv[mt] = lutS[pBase + mt * 16 + (lane & 7) + ((lane >> 3) & 1) * 8];

    for (int tap = 0; tap < 9; ++tap) {
        {   // stage W[tap] (image already swizzled)
            const uint4* wsrc = (const uint4*)(g_w2f + (size_t)(t * 9 + tap) * 8192);
            uint4* wdst = (uint4*)(sm + C2_AB);
            wdst[tid] = wsrc[tid];
            wdst[tid + 512] = wsrc[tid + 512];
        }
        __syncthreads();
        const uint32_t tapOff = (uint32_t)(((tap / 3) * 32 + (tap % 3)) * 128);
        #pragma unroll
        for (int ks = 0; ks < 4; ++ks) {
            const uint32_t kb = ks * 32;
            uint32_t a[3][4], b[4][2];
            #pragma unroll
            for (int mt = 0; mt < 3; ++mt)
                ldsm_x4(a[mt], aBase + sw128(lutv[mt] + tapOff + kb + aKoff));
            #pragma unroll
            for (int nt = 0; nt < 4; ++nt)
                ldsm_x2(b[nt], wBase + sw128(bRowK + nt * 1024 + kb));
            #pragma unroll
            for (int mt = 0; mt < 3; ++mt)
                #pragma unroll
                for (int nt = 0; nt < 4; ++nt)
                    mma16816(acc[mt][nt], a[mt], b[nt]);
        }
        __syncthreads();
    }

    // epilogue: v = crelu(triangle(d)) -> vbuf, then alpha-pool -> g_a2f
    const float tw = tri_w[t * 3 + 1], inv_tw = 1.f / tw;
    const float cb = crelu_b[t * 3 + 1];
    const float al = sfm_alpha[t * 2 + 1];
    const float c00 = al * al * al * 0.25f, c01 = al * al * 0.25f;
    const float c10 = al * 0.25f, c11 = 0.25f;
    float* vbuf = (float*)sm;   // [192][130]

    #pragma unroll
    for (int mt = 0; mt < 3; ++mt)
        #pragma unroll
        for (int nt = 0; nt < 4; ++nt)
            #pragma unroll
            for (int e = 0; e < 4; ++e) {
                int p = pBase + mt * 16 + (lane >> 2) + (e >= 2 ? 8 : 0);
                int oc = nBase + nt * 8 + 2 * (lane & 3) + (e & 1);
                float d = fmaxf(xsqS[p] - 2.f * acc[mt][nt][e] + wsqS[oc], 0.f);
                float v = 1.f - fminf(d, tw) * inv_tw;
                vbuf[p * 130 + oc] = (v >= cb) ? v : 0.f;
            }
    __syncthreads();

    #pragma unroll
    for (int u = 0; u < 12; ++u) {
        int idx = tid + u * 512;
        int oc = idx & 127, q = idx >> 7;       // q: 0..47
        int pr = q / 12, pc = q % 12;
        int p00 = (2 * pr) * 24 + 2 * pc;
        float pooled = c00 * vbuf[p00 * 130 + oc] + c01 * vbuf[(p00 + 1) * 130 + oc]
                     + c10 * vbuf[(p00 + 24) * 130 + oc] + c11 * vbuf[(p00 + 25) * 130 + oc];
        int gi = ytile * 4 + pr;
        g_a2f[((size_t)bt * 224 + (gi + 1) * 16 + (pc + 1)) * 128 + oc] = __float2half(pooled);
    }
}

// ---------------- conv3: implicit GEMM via mma.sync ----------------
// grid (NBT, 2): oc half.  384 thr = 12 warps (3M x 4N).
// M = 144 positions, N = 128 oc, K = 9 taps x 128 ch (2 k-planes).
#define C3_AP 28672                 // per-plane A bytes (224 cells x 128B)
#define C3_WB 57344                 // W offset
#define C3_DYN 90112

__global__ void __launch_bounds__(384) k_conv3(
    const float* __restrict__ tri_w, const float* __restrict__ crelu_b)
{
    extern __shared__ __align__(1024) unsigned char sm[];
    __shared__ uint32_t lutS[144];
    __shared__ float xsqS[144];
    __shared__ float wsqS[128];

    const int bt = blockIdx.x, t = bt % NT, b = bt / NT;
    const int half = blockIdx.y;
    const int tid = threadIdx.x, wid = tid >> 5, lane = tid & 31;
    const uint32_t aBase = smem_u32(sm);
    const uint32_t wBase = aBase + C3_WB;

    {   // stage A: 224 cells x 256B, split into 2 k-planes of 128B rows
        const uint4* src = (const uint4*)(g_a2f + (size_t)bt * 224 * 128);
        for (int idx = tid; idx < 3584; idx += 384) {
            int cell = idx >> 4, chunk = idx & 15;
            uint32_t off = (uint32_t)((chunk >> 3) * C3_AP)
                         + sw128((uint32_t)(cell * 128 + (chunk & 7) * 16));
            *(uint4*)(sm + off) = src[idx];
        }
    }
    if (tid < 144) {
        int r = tid / 12, c = tid % 12;
        lutS[tid] = (uint32_t)((r * 16 + c) * 128);
        xsqS[tid] = g_xsq3[bt * 144 + tid];
    }
    if (tid < 128) wsqS[tid] = g_wsq3[t * 256 + half * 128 + tid];

    const int wm = wid >> 2, wn = wid & 3;    // wm 0..2, wn 0..3
    const int pBase = wm * 48, nBase = wn * 32;
    const int l15 = lane & 15;
    const uint32_t aKoff = ((lane >> 4) & 1) * 16;
    const uint32_t bRowK = (uint32_t)((nBase + (l15 & 7)) * 128 + ((l15 >> 3) & 1) * 16);

    float acc[3][4][4];
    #pragma unroll
    for (int mt = 0; mt < 3; ++mt)
        #pragma unroll
        for (int nt = 0; nt < 4; ++nt)
            #pragma unroll
            for (int e = 0; e < 4; ++e) acc[mt][nt][e] = 0.f;

    __syncthreads();
    uint32_t lutv[3];
    #pragma unroll
    for (int mt = 0; mt < 3; ++mt)
        lutv[mt] = lutS[pBase + mt * 16 + (lane & 7) + ((lane >> 3) & 1) * 8];

    for (int tap = 0; tap < 9; ++tap) {
        {   // stage W[tap]: 2 planes x 16KB, image pre-swizzled
            const uint4* wsrc = (const uint4*)(g_w3f + (size_t)(((t * 2 + half) * 9 + tap)) * 16384);
            uint4* wdst = (uint4*)(sm + C3_WB);
            for (int i = tid; i < 2048; i += 384) wdst[i] = wsrc[i];
        }
        __syncthreads();
        const uint32_t tapOff = (uint32_t)(((tap / 3) * 16 + (tap % 3)) * 128);
        #pragma unroll
        for (int ks = 0; ks < 8; ++ks) {
            const uint32_t plane = (ks >> 2) ? C3_AP : 0;
            const uint32_t wplane = (ks >> 2) ? 16384u : 0;
            const uint32_t kb = (ks & 3) * 32;
            uint32_t a[3][4], b[4][2];
            #pragma unroll
            for (int mt = 0; mt < 3; ++mt)
                ldsm_x4(a[mt], aBase + plane + sw128(lutv[mt] + tapOff + kb + aKoff));
            #pragma unroll
            for (int nt = 0; nt < 4; ++nt)
                ldsm_x2(b[nt], wBase + wplane + sw128(bRowK + nt * 1024 + kb));
            #pragma unroll
            for (int mt = 0; mt < 3; ++mt)
                #pragma unroll
                for (int nt = 0; nt < 4; ++nt)
                    mma16816(acc[mt][nt], a[mt], b[nt]);
        }
        __syncthreads();
    }

    // epilogue: direct stores (g_a3 planar [oc][pos])
    const float tw = tri_w[t * 3 + 2], inv_tw = 1.f / tw;
    const float cb = crelu_b[t * 3 + 2];
    float* outG = g_a3 + (size_t)b * 110592 + t * 36864 + half * 128 * 144;

    #pragma unroll
    for (int mt = 0; mt < 3; ++mt)
        #pragma unroll
        for (int nt = 0; nt < 4; ++nt)
            #pragma unroll
            for (int e = 0; e < 4; ++e) {
                int p = pBase + mt * 16 + (lane >> 2) + (e >= 2 ? 8 : 0);
                int oc = nBase + nt * 8 + 2 * (lane & 3) + (e & 1);
                float d = fmaxf(xsqS[p] - 2.f * acc[mt][nt][e] + wsqS[oc], 0.f);
                float v = 1.f - fminf(d, tw) * inv_tw;
                outG[oc * 144 + p] = (v >= cb) ? v : 0.f;
            }
}

// ---------------- FC (fp32 SIMT, proven) ----------------
__global__ void __launch_bounds__(320) k_fc_partial(const float* __restrict__ fcw) {
    __shared__ __align__(16) float w_s[100 * 32];
    __shared__ __align__(16) float a_s[128 * 34];

    const int blk = blockIdx.x, tid = threadIdx.x;
    const int k0 = blk * FC_SLAB_K;
    const int ng = tid / 16, bq = tid % 16;
    const int n0 = ng * 5;

    float acc[5][8];
    #pragma unroll
    for (int qn = 0; qn < 5; ++qn)
        #pragma unroll
        for (int r = 0; r < 8; ++r) acc[qn][r] = 0.f;

    for (int ch = 0; ch < 16; ++ch) {
        int kb = k0 + ch * 32;
        __syncthreads();
        for (int idx = tid; idx < 100 * 32; idx += 320)
            w_s[idx] = fcw[(idx >> 5) * 110592 + kb + (idx & 31)];
        for (int idx = tid; idx < 128 * 32; idx += 320) {
            int bb = idx >> 5, kk = idx & 31;
            a_s[bb * 34 + kk] = g_a3[bb * 110592 + kb + kk];
        }
        __syncthreads();
        #pragma unroll 4
        for (int kk = 0; kk < 32; kk += 2) {
            float2 av[8];
            #pragma unroll
            for (int r = 0; r < 8; ++r)
                av[r] = *(const float2*)&a_s[(bq + 16 * r) * 34 + kk];
            #pragma unroll
            for (int qn = 0; qn < 5; ++qn) {
                float2 wv = *(const float2*)&w_s[(n0 + qn) * 32 + kk];
                #pragma unroll
                for (int r = 0; r < 8; ++r)
                    acc[qn][r] += wv.x * av[r].x + wv.y * av[r].y;
            }
        }
    }
    #pragma unroll
    for (int qn = 0; qn < 5; ++qn)
        #pragma unroll
        for (int r = 0; r < 8; ++r)
            g_part[blk * 12800 + (bq + 16 * r) * 100 + n0 + qn] = acc[qn][r];
}

__global__ void k_fc_reduce(const float* __restrict__ fcb, float* __restrict__ out) {
    int idx = blockIdx.x * blockDim.x + threadIdx.x;
    if (idx >= NB * 100) return;
    int n = idx % 100;
    float s = fcb[n];
    for (int sb = 0; sb < FC_SLABS; ++sb) s += g_part[sb * 12800 + idx];
    out[idx] = s;
}

// ---------------------------------------------------------------------------
extern "C" void kernel_launch(void* const* d_in, const int* in_sizes, int n_in,
                              void* d_out, int out_size) {
    const float* x         = (const float*)d_in[0];
    const float* W1        = (const float*)d_in[1];
    const float* W2        = (const float*)d_in[2];
    const float* W3        = (const float*)d_in[3];
    const float* tri_w     = (const float*)d_in[4];
    const float* crelu_b   = (const float*)d_in[5];
    const float* sfm_alpha = (const float*)d_in[6];
    const float* fcw       = (const float*)d_in[7];
    const float* fcb       = (const float*)d_in[8];
    float* out = (float*)d_out;

    static int attr_done = 0;
    if (!attr_done) {
        cudaFuncSetAttribute(k_conv2, cudaFuncAttributeMaxDynamicSharedMemorySize, C2_DYN);
        cudaFuncSetAttribute(k_conv3, cudaFuncAttributeMaxDynamicSharedMemorySize, C3_DYN);
        attr_done = 1;
    }

    k_zero<<<(int)((sizeof(g_a1f) + sizeof(g_a2f)) / 16 + 255) / 256, 256>>>();
    k_prep<<<4320, 256>>>(W2, W3);
    k_wsq<<<5, 256>>>(W2, W3);
    k_layer1<<<NBT, 256>>>(x, W1, tri_w, crelu_b, sfm_alpha);
    k_xsq2<<<NBT, 256>>>();
    k_conv2<<<dim3(NBT, 3), 512, C2_DYN>>>(tri_w, crelu_b, sfm_alpha);
    k_xsq3<<<NBT, 256>>>();
    k_conv3<<<dim3(NBT, 2), 384, C3_DYN>>>(tri_w, crelu_b);
    k_fc_partial<<<FC_SLABS, 320>>>(fcw);
    k_fc_reduce<<<(NB * 100 + 255) / 256, 256>>>(fcb, out);
}

// round 5
// speedup vs baseline: 4.3218x; 1.4821x over previous
#include <cuda_runtime.h>
#include <cuda_fp16.h>
#include <cstdint>

#define NB 128
#define NT 3
#define NBT (NB*NT)

// ---------------- scratch ----------------
__device__ __align__(16) __half g_a1f[NBT * 832 * 64];    // padded 26x32, ch-last
__device__ __align__(16) __half g_a2f[NBT * 224 * 128];   // padded 14x16, ch-last
__device__ __align__(16) __half g_a3h[NB * 110592];
__device__ __align__(16) __half g_a3l[NB * 110592];
__device__ __align__(16) __half g_fwh[100 * 110592];
__device__ __align__(16) __half g_fwl[100 * 110592];
__device__ float g_xsq2[NBT * 576];
__device__ float g_xsq3[NBT * 144];
__device__ float g_wsq2[NT * 128];
__device__ float g_wsq3[NT * 256];
__device__ __align__(16) __half g_w2f[27 * 8192];
__device__ __align__(16) __half g_w3f[54 * 16384];

#define FC_SLABS 216
#define FC_SLAB_K 512
__device__ float g_part[FC_SLABS * NB * 100];

// ---------------- helpers ----------------
static __device__ __forceinline__ uint32_t smem_u32(const void* p) {
    uint32_t a;
    asm("{ .reg .u64 t; cvta.to.shared.u64 t, %1; cvt.u32.u64 %0, t; }" : "=r"(a) : "l"(p));
    return a;
}
static __device__ __forceinline__ uint32_t sw128(uint32_t off) {
    return off ^ ((off >> 3) & 0x70);
}
static __device__ __forceinline__ void ldsm_x4(uint32_t* r, uint32_t addr) {
    asm volatile("ldmatrix.sync.aligned.m8n8.x4.shared.b16 {%0,%1,%2,%3}, [%4];"
                 : "=r"(r[0]), "=r"(r[1]), "=r"(r[2]), "=r"(r[3]) : "r"(addr));
}
static __device__ __forceinline__ void ldsm_x2(uint32_t* r, uint32_t addr) {
    asm volatile("ldmatrix.sync.aligned.m8n8.x2.shared.b16 {%0,%1}, [%2];"
                 : "=r"(r[0]), "=r"(r[1]) : "r"(addr));
}
static __device__ __forceinline__ void mma16816(float* d, const uint32_t* a, const uint32_t* b) {
    asm volatile("mma.sync.aligned.m16n8k16.row.col.f32.f16.f16.f32 "
                 "{%0,%1,%2,%3}, {%4,%5,%6,%7}, {%8,%9}, {%0,%1,%2,%3};"
                 : "+f"(d[0]), "+f"(d[1]), "+f"(d[2]), "+f"(d[3])
                 : "r"(a[0]), "r"(a[1]), "r"(a[2]), "r"(a[3]), "r"(b[0]), "r"(b[1]));
}

// ---------------- zero padded activation buffers ----------------
__global__ void k_zero() {
    size_t i = (size_t)blockIdx.x * 256 + threadIdx.x;
    const size_t n1 = sizeof(g_a1f) / 16, n2 = sizeof(g_a2f) / 16;
    uint4 z = {0u, 0u, 0u, 0u};
    if (i < n1) ((uint4*)g_a1f)[i] = z;
    else if (i < n1 + n2) ((uint4*)g_a2f)[i - n1] = z;
}

// ---------------- prep: swizzled weight images + fc hi/lo split ----------------
__global__ void k_prep(const float* __restrict__ W2, const float* __restrict__ W3,
                       const float* __restrict__ fcw) {
    int e = blockIdx.x * blockDim.x + threadIdx.x;
    if (e < 221184) {                         // t, tap, oc(128), k(64)
        int k = e & 63, oc = (e >> 6) & 127;
        int tap = (e >> 13) % 9, t = e / (9 * 8192);
        float w = W2[(t * 128 + oc) * 576 + k * 9 + tap];
        uint32_t sw = sw128((uint32_t)(oc * 128 + k * 2));
        *(__half*)((char*)(g_w2f + (size_t)(t * 9 + tap) * 8192) + sw) = __float2half(w);
    } else if (e < 1105920) {                 // t, half, tap, oc(128), k(128)
        int e2 = e - 221184;
        int k = e2 & 127, oc = (e2 >> 7) & 127;
        int tap = (e2 >> 14) % 9, th = e2 / (9 * 16384);
        int t = th >> 1, half = th & 1;
        float w = W3[(t * 256 + half * 128 + oc) * 1152 + k * 9 + tap];
        uint32_t off = (uint32_t)((k >> 6) * 16384) + sw128((uint32_t)(oc * 128 + (k & 63) * 2));
        *(__half*)((char*)(g_w3f + (size_t)(th * 9 + tap) * 16384) + off) = __float2half(w);
    } else if (e < 1105920 + 11059200) {      // fc weight hi/lo split
        int e2 = e - 1105920;
        float w = fcw[e2];
        __half hi = __float2half(w);
        g_fwh[e2] = hi;
        g_fwl[e2] = __float2half(w - __half2float(hi));
    }
}

// wsq: one warp per output channel, shfl reduce
__global__ void __launch_bounds__(256) k_wsq(const float* __restrict__ W2,
                                             const float* __restrict__ W3) {
    int oid = blockIdx.x * 8 + (threadIdx.x >> 5);
    int lane = threadIdx.x & 31;
    float s = 0.f;
    if (oid < NT * 128) {
        const float* p = W2 + oid * 576;
        for (int k = lane; k < 576; k += 32) {
            float w = __half2float(__float2half(p[k])); s += w * w;
        }
    } else {
        const float* p = W3 + (oid - NT * 128) * 1152;
        for (int k = lane; k < 1152; k += 32) {
            float w = __half2float(__float2half(p[k])); s += w * w;
        }
    }
    #pragma unroll
    for (int d = 16; d > 0; d >>= 1) s += __shfl_xor_sync(0xffffffffu, s, d);
    if (lane == 0) {
        if (oid < NT * 128) g_wsq2[oid] = s;
        else g_wsq3[oid - NT * 128] = s;
    }
}

// ---------------- layer 1: fp32 SIMT, y-split (grid NBT x 2) ----------------
__global__ void __launch_bounds__(256) k_layer1(
    const float* __restrict__ x, const float* __restrict__ W1,
    const float* __restrict__ tri_w, const float* __restrict__ crelu_b,
    const float* __restrict__ sfm_alpha)
{
    __shared__ __align__(16) float xpadL[28 * 52];
    __shared__ float xsqL[24 * 48];
    __shared__ float w1s[64 * 25];
    __shared__ float wsq1s[64];

    const int bt = blockIdx.x, t = bt % NT, h = blockIdx.y, tid = threadIdx.x;

    for (int idx = tid; idx < 28 * 52; idx += 256) {
        int r = idx / 52, c = idx % 52;
        int gr = h * 24 + r - 2, gc = c - 2;
        xpadL[idx] = (gr >= 0 && gr < 48 && gc >= 0 && gc < 48)
                   ? x[bt * 2304 + gr * 48 + gc] : 0.f;
    }
    for (int idx = tid; idx < 1600; idx += 256) w1s[idx] = W1[t * 1600 + idx];
    __syncthreads();

    if (tid < 64) {
        float s = 0.f;
        #pragma unroll
        for (int k = 0; k < 25; ++k) { float w = w1s[tid * 25 + k]; s += w * w; }
        wsq1s[tid] = s;
    }
    for (int idx = tid; idx < 24 * 48; idx += 256) {
        int y = idx / 48, xx = idx % 48;
        float s = 0.f;
        #pragma unroll
        for (int ky = 0; ky < 5; ++ky)
            #pragma unroll
            for (int kx = 0; kx < 5; ++kx) {
                float v = xpadL[(y + ky) * 52 + xx + kx];
                s += v * v;
            }
        xsqL[idx] = s;
    }
    __syncthreads();

    const int o = tid >> 2, sub = tid & 3;
    float wr[25];
    #pragma unroll
    for (int k = 0; k < 25; ++k) wr[k] = w1s[o * 25 + k];
    const float wq = wsq1s[o];
    const float tw = tri_w[t * 3 + 0], inv_tw = 1.f / tw;
    const float cb = crelu_b[t * 3 + 0];
    const float al = sfm_alpha[t * 2 + 0];
    const float c00 = al * al * al * 0.25f, c01 = al * al * 0.25f;
    const float c10 = al * 0.25f, c11 = 0.25f;

    for (int it = 0; it < 72; ++it) {
        int p = it * 4 + sub;                  // 288 pooled positions (12x24 local)
        int i = p / 24, j = p % 24;
        float pt[6][6];
        #pragma unroll
        for (int r = 0; r < 6; ++r) {
            const float* row = &xpadL[(2 * i + r) * 52 + 2 * j];
            #pragma unroll
            for (int s2 = 0; s2 < 3; ++s2) {
                float2 u = *(const float2*)(row + 2 * s2);
                pt[r][2 * s2] = u.x; pt[r][2 * s2 + 1] = u.y;
            }
        }
        float vv[2][2];
        #pragma unroll
        for (int a = 0; a < 2; ++a)
            #pragma unroll
            for (int b2 = 0; b2 < 2; ++b2) {
                float cr = 0.f;
                #pragma unroll
                for (int ky = 0; ky < 5; ++ky)
                    #pragma unroll
                    for (int kx = 0; kx < 5; ++kx)
                        cr += wr[ky * 5 + kx] * pt[a + ky][b2 + kx];
                float d = xsqL[(2 * i + a) * 48 + 2 * j + b2] - 2.f * cr + wq;
                d = fmaxf(d, 0.f);
                float v = 1.f - fminf(d, tw) * inv_tw;
                vv[a][b2] = (v >= cb) ? v : 0.f;
            }
        float pooled = c00 * vv[0][0] + c01 * vv[0][1] + c10 * vv[1][0] + c11 * vv[1][1];
        int gi = h * 12 + i;
        g_a1f[((size_t)bt * 832 + (gi + 1) * 32 + (j + 1)) * 64 + o] = __float2half(pooled);
    }
}

// ---------------- xsq maps ----------------
__global__ void __launch_bounds__(256) k_xsq2() {
    __shared__ float spad[26 * 26];
    const int bt = blockIdx.x, tid = threadIdx.x;
    for (int i = tid; i < 676; i += 256) spad[i] = 0.f;
    __syncthreads();
    for (int p = tid; p < 576; p += 256) {
        int y = p / 24, x = p % 24;
        const __half2* hp = (const __half2*)(g_a1f + ((size_t)bt * 832 + (y + 1) * 32 + x + 1) * 64);
        float acc = 0.f;
        #pragma unroll
        for (int c = 0; c < 32; ++c) {
            float2 f = __half22float2(hp[c]);
            acc += f.x * f.x + f.y * f.y;
        }
        spad[(y + 1) * 26 + (x + 1)] = acc;
    }
    __syncthreads();
    for (int p = tid; p < 576; p += 256) {
        int y = p / 24, x = p % 24;
        float acc = 0.f;
        #pragma unroll
        for (int r = 0; r < 3; ++r)
            #pragma unroll
            for (int cx = 0; cx < 3; ++cx)
                acc += spad[(y + r) * 26 + x + cx];
        g_xsq2[bt * 576 + p] = acc;
    }
}

__global__ void __launch_bounds__(256) k_xsq3() {
    __shared__ float spad[14 * 14];
    const int bt = blockIdx.x, tid = threadIdx.x;
    for (int i = tid; i < 196; i += 256) spad[i] = 0.f;
    __syncthreads();
    if (tid < 144) {
        int y = tid / 12, x = tid % 12;
        const __half2* hp = (const __half2*)(g_a2f + ((size_t)bt * 224 + (y + 1) * 16 + x + 1) * 128);
        float acc = 0.f;
        #pragma unroll
        for (int c = 0; c < 64; ++c) {
            float2 f = __half22float2(hp[c]);
            acc += f.x * f.x + f.y * f.y;
        }
        spad[(y + 1) * 14 + (x + 1)] = acc;
    }
    __syncthreads();
    if (tid < 144) {
        int y = tid / 12, x = tid % 12;
        float acc = 0.f;
        #pragma unroll
        for (int r = 0; r < 3; ++r)
            #pragma unroll
            for (int cx = 0; cx < 3; ++cx)
                acc += spad[(y + r) * 14 + x + cx];
        g_xsq3[bt * 144 + tid] = acc;
    }
}

// ---------------- conv2: implicit GEMM, double-buffered W ----------------
#define C2_AB 40960
#define C2_DYN 99840

__global__ void __launch_bounds__(512) k_conv2(
    const float* __restrict__ tri_w, const float* __restrict__ crelu_b,
    const float* __restrict__ sfm_alpha)
{
    extern __shared__ __align__(1024) unsigned char sm[];
    __shared__ uint32_t lutS[192];
    __shared__ float xsqS[192];
    __shared__ float wsqS[128];

    const int bt = blockIdx.x, t = bt % NT, ytile = blockIdx.y;
    const int y0 = ytile * 8;
    const int tid = threadIdx.x, wid = tid >> 5, lane = tid & 31;
    const uint32_t aBase = smem_u32(sm);
    const uint32_t wBase = aBase + C2_AB;

    {   // stage A: padded rows y0..y0+9 (320 cells)
        const uint4* src = (const uint4*)(g_a1f + ((size_t)bt * 832 + y0 * 32) * 64);
        #pragma unroll
        for (int u = 0; u < 5; ++u) {
            int idx = tid + u * 512;
            uint32_t off = sw128((uint32_t)((idx >> 3) * 128 + (idx & 7) * 16));
            *(uint4*)(sm + off) = src[idx];
        }
    }
    {   // stage W tap 0 into buf 0
        const uint4* wsrc = (const uint4*)(g_w2f + (size_t)(t * 9) * 8192);
        uint4* wdst = (uint4*)(sm + C2_AB);
        wdst[tid] = wsrc[tid];
        wdst[tid + 512] = wsrc[tid + 512];
    }
    if (tid < 192) {
        int r = tid / 24, c = tid % 24;
        lutS[tid] = (uint32_t)((r * 32 + c) * 128);
        xsqS[tid] = g_xsq2[bt * 576 + y0 * 24 + tid];
    }
    if (tid < 128) wsqS[tid] = g_wsq2[t * 128 + tid];

    const int wm = wid >> 2, wn = wid & 3;
    const int pBase = wm * 48, nBase = wn * 32;
    const int l15 = lane & 15;
    const uint32_t aKoff = ((lane >> 4) & 1) * 16;
    const uint32_t bRowK = (uint32_t)((nBase + (l15 & 7)) * 128 + ((l15 >> 3) & 1) * 16);

    float acc[3][4][4];
    #pragma unroll
    for (int mt = 0; mt < 3; ++mt)
        #pragma unroll
        for (int nt = 0; nt < 4; ++nt)
            #pragma unroll
            for (int e = 0; e < 4; ++e) acc[mt][nt][e] = 0.f;

    __syncthreads();
    uint32_t lutv[3];
    #pragma unroll
    for (int mt = 0; mt < 3; ++mt)
        lutv[mt] = lutS[pBase + mt * 16 + (lane & 7) + ((lane >> 3) & 1) * 8];

    for (int tap = 0; tap < 9; ++tap) {
        if (tap < 8) {   // prefetch next tap into other buffer
            const uint4* wsrc = (const uint4*)(g_w2f + (size_t)(t * 9 + tap + 1) * 8192);
            uint4* wdst = (uint4*)(sm + C2_AB + (((tap + 1) & 1) << 14));
            wdst[tid] = wsrc[tid];
            wdst[tid + 512] = wsrc[tid + 512];
        }
        const uint32_t wb = wBase + ((tap & 1) << 14);
        const uint32_t tapOff = (uint32_t)(((tap / 3) * 32 + (tap % 3)) * 128);
        #pragma unroll
        for (int ks = 0; ks < 4; ++ks) {
            const uint32_t kb = ks * 32;
            uint32_t a[3][4], b[4][2];
            #pragma unroll
            for (int mt = 0; mt < 3; ++mt)
                ldsm_x4(a[mt], aBase + sw128(lutv[mt] + tapOff + kb + aKoff));
            #pragma unroll
            for (int nt = 0; nt < 4; ++nt)
                ldsm_x2(b[nt], wb + sw128(bRowK + nt * 1024 + kb));
            #pragma unroll
            for (int mt = 0; mt < 3; ++mt)
                #pragma unroll
                for (int nt = 0; nt < 4; ++nt)
                    mma16816(acc[mt][nt], a[mt], b[nt]);
        }
        __syncthreads();
    }

    const float tw = tri_w[t * 3 + 1], inv_tw = 1.f / tw;
    const float cb = crelu_b[t * 3 + 1];
    const float al = sfm_alpha[t * 2 + 1];
    const float c00 = al * al * al * 0.25f, c01 = al * al * 0.25f;
    const float c10 = al * 0.25f, c11 = 0.25f;
    float* vbuf = (float*)sm;   // [192][130]

    #pragma unroll
    for (int mt = 0; mt < 3; ++mt)
        #pragma unroll
        for (int nt = 0; nt < 4; ++nt)
            #pragma unroll
            for (int e = 0; e < 4; ++e) {
                int p = pBase + mt * 16 + (lane >> 2) + (e >= 2 ? 8 : 0);
                int oc = nBase + nt * 8 + 2 * (lane & 3) + (e & 1);
                float d = fmaxf(xsqS[p] - 2.f * acc[mt][nt][e] + wsqS[oc], 0.f);
                float v = 1.f - fminf(d, tw) * inv_tw;
                vbuf[p * 130 + oc] = (v >= cb) ? v : 0.f;
            }
    __syncthreads();

    #pragma unroll
    for (int u = 0; u < 12; ++u) {
        int idx = tid + u * 512;
        int oc = idx & 127, q = idx >> 7;
        int pr = q / 12, pc = q % 12;
        int p00 = (2 * pr) * 24 + 2 * pc;
        float pooled = c00 * vbuf[p00 * 130 + oc] + c01 * vbuf[(p00 + 1) * 130 + oc]
                     + c10 * vbuf[(p00 + 24) * 130 + oc] + c11 * vbuf[(p00 + 25) * 130 + oc];
        int gi = ytile * 4 + pr;
        g_a2f[((size_t)bt * 224 + (gi + 1) * 16 + (pc + 1)) * 128 + oc] = __float2half(pooled);
    }
}

// ---------------- conv3: implicit GEMM, double-buffered W planes ----------------
#define C3_AP 28672
#define C3_WB 57344
#define C3_DYN 90112

__global__ void __launch_bounds__(384) k_conv3(
    const float* __restrict__ tri_w, const float* __restrict__ crelu_b)
{
    extern __shared__ __align__(1024) unsigned char sm[];
    __shared__ uint32_t lutS[144];
    __shared__ float xsqS[144];
    __shared__ float wsqS[128];

    const int bt = blockIdx.x, t = bt % NT, b = bt / NT;
    const int half = blockIdx.y;
    const int tid = threadIdx.x, wid = tid >> 5, lane = tid & 31;
    const uint32_t aBase = smem_u32(sm);
    const uint32_t wBase = aBase + C3_WB;
    const size_t wImgBase = (size_t)((t * 2 + half) * 9) * 2048;   // uint4 units

    {   // stage A: 224 cells x 256B, 2 k-planes
        const uint4* src = (const uint4*)(g_a2f + (size_t)bt * 224 * 128);
        for (int idx = tid; idx < 3584; idx += 384) {
            int cell = idx >> 4, chunk = idx & 15;
            uint32_t off = (uint32_t)((chunk >> 3) * C3_AP)
                         + sw128((uint32_t)(cell * 128 + (chunk & 7) * 16));
            *(uint4*)(sm + off) = src[idx];
        }
    }
    {   // stage W step 0 (tap 0, plane 0) into buf 0
        const uint4* wsrc = (const uint4*)g_w3f + wImgBase;
        uint4* wdst = (uint4*)(sm + C3_WB);
        for (int i = tid; i < 1024; i += 384) wdst[i] = wsrc[i];
    }
    if (tid < 144) {
        int r = tid / 12, c = tid % 12;
        lutS[tid] = (uint32_t)((r * 16 + c) * 128);
        xsqS[tid] = g_xsq3[bt * 144 + tid];
    }
    if (tid < 128) wsqS[tid] = g_wsq3[t * 256 + half * 128 + tid];

    const int wm = wid >> 2, wn = wid & 3;
    const int pBase = wm * 48, nBase = wn * 32;
    const int l15 = lane & 15;
    const uint32_t aKoff = ((lane >> 4) & 1) * 16;
    const uint32_t bRowK = (uint32_t)((nBase + (l15 & 7)) * 128 + ((l15 >> 3) & 1) * 16);

    float acc[3][4][4];
    #pragma unroll
    for (int mt = 0; mt < 3; ++mt)
        #pragma unroll
        for (int nt = 0; nt < 4; ++nt)
            #pragma unroll
            for (int e = 0; e < 4; ++e) acc[mt][nt][e] = 0.f;

    __syncthreads();
    uint32_t lutv[3];
    #pragma unroll
    for (int mt = 0; mt < 3; ++mt)
        lutv[mt] = lutS[pBase + mt * 16 + (lane & 7) + ((lane >> 3) & 1) * 8];

    for (int s = 0; s < 18; ++s) {             // (tap, plane) steps
        if (s < 17) {                          // prefetch next step
            int s1 = s + 1, tap1 = s1 >> 1, pl1 = s1 & 1;
            const uint4* wsrc = (const uint4*)g_w3f + wImgBase + tap1 * 2048 + pl1 * 1024;
            uint4* wdst = (uint4*)(sm + C3_WB + ((s1 & 1) << 14));
            for (int i = tid; i < 1024; i += 384) wdst[i] = wsrc[i];
        }
        const int tap = s >> 1, pl = s & 1;
        const uint32_t aplane = pl ? (uint32_t)C3_AP : 0u;
        const uint32_t wb = wBase + ((s & 1) << 14);
        const uint32_t tapOff = (uint32_t)(((tap / 3) * 16 + (tap % 3)) * 128);
        #pragma unroll
        for (int ks = 0; ks < 4; ++ks) {
            const uint32_t kb = ks * 32;
            uint32_t a[3][4], b[4][2];
            #pragma unroll
            for (int mt = 0; mt < 3; ++mt)
                ldsm_x4(a[mt], aBase + aplane + sw128(lutv[mt] + tapOff + kb + aKoff));
            #pragma unroll
            for (int nt = 0; nt < 4; ++nt)
                ldsm_x2(b[nt], wb + sw128(bRowK + nt * 1024 + kb));
            #pragma unroll
            for (int mt = 0; mt < 3; ++mt)
                #pragma unroll
                for (int nt = 0; nt < 4; ++nt)
                    mma16816(acc[mt][nt], a[mt], b[nt]);
        }
        __syncthreads();
    }

    // epilogue: hi/lo split staged via smem for coalesced global stores
    const float tw = tri_w[t * 3 + 2], inv_tw = 1.f / tw;
    const float cb = crelu_b[t * 3 + 2];
    __half2* sOut = (__half2*)sm;    // [128][144] half2 = 73728 B (MMA done)

    #pragma unroll
    for (int mt = 0; mt < 3; ++mt)
        #pragma unroll
        for (int nt = 0; nt < 4; ++nt)
            #pragma unroll
            for (int e = 0; e < 4; ++e) {
                int p = pBase + mt * 16 + (lane >> 2) + (e >= 2 ? 8 : 0);
                int oc = nBase + nt * 8 + 2 * (lane & 3) + (e & 1);
                float d = fmaxf(xsqS[p] - 2.f * acc[mt][nt][e] + wsqS[oc], 0.f);
                float v = 1.f - fminf(d, tw) * inv_tw;
                v = (v >= cb) ? v : 0.f;
                __half hi = __float2half(v);
                __half lo = __float2half(v - __half2float(hi));
                sOut[oc * 144 + p] = __halves2half2(hi, lo);
            }
    __syncthreads();
    size_t base = (size_t)b * 110592 + t * 36864 + half * 18432;
    for (int idx = tid; idx < 18432; idx += 384) {
        __half2 hv = sOut[idx];
        g_a3h[base + idx] = __low2half(hv);
        g_a3l[base + idx] = __high2half(hv);
    }
}

// ---------------- FC: fp16 mma, 3-pass hi/lo, split-K ----------------
__global__ void __launch_bounds__(256) k_fc_mma() {
    __shared__ __align__(16) unsigned char aHs[8192];
    __shared__ __align__(16) unsigned char aLs[8192];
    __shared__ __align__(16) unsigned char wHs[6656];
    __shared__ __align__(16) unsigned char wLs[6656];

    const int blk = blockIdx.x, tid = threadIdx.x, wid = tid >> 5, lane = tid & 31;
    const int k0 = blk * FC_SLAB_K;
    const uint32_t aH = smem_u32(aHs), aL = smem_u32(aLs);
    const uint32_t wH = smem_u32(wHs), wL = smem_u32(wLs);

    float acc[13][4];
    #pragma unroll
    for (int nt = 0; nt < 13; ++nt)
        #pragma unroll
        for (int e = 0; e < 4; ++e) acc[nt][e] = 0.f;

    const int mBase = wid * 16;
    const uint32_t aRow = (uint32_t)(mBase + (lane & 7) + ((lane >> 3) & 1) * 8);
    const uint32_t aK16 = ((lane >> 4) & 1) * 16;
    const uint32_t bK16 = ((lane >> 3) & 1) * 16;
    const uint32_t bRowSel = ((lane >> 4) & 1) * 8 + (lane & 7);

    for (int ch = 0; ch < 16; ++ch) {
        int kb = k0 + ch * 32;
        __syncthreads();
        for (int idx = tid; idx < 512; idx += 256) {
            int r = idx >> 2, c = idx & 3;
            uint32_t sw = sw128((uint32_t)(r * 64 + c * 16));
            *(uint4*)(aHs + sw) = *(const uint4*)(g_a3h + (size_t)r * 110592 + kb + c * 8);
            *(uint4*)(aLs + sw) = *(const uint4*)(g_a3l + (size_t)r * 110592 + kb + c * 8);
        }
        for (int idx = tid; idx < 416; idx += 256) {
            int r = idx >> 2, c = idx & 3;
            uint32_t sw = sw128((uint32_t)(r * 64 + c * 16));
            uint4 vh = {0u, 0u, 0u, 0u}, vl = {0u, 0u, 0u, 0u};
            if (r < 100) {
                vh = *(const uint4*)(g_fwh + (size_t)r * 110592 + kb + c * 8);
                vl = *(const uint4*)(g_fwl + (size_t)r * 110592 + kb + c * 8);
            }
            *(uint4*)(wHs + sw) = vh;
            *(uint4*)(wLs + sw) = vl;
        }
        __syncthreads();

        #pragma unroll
        for (int ks = 0; ks < 2; ++ks) {
            uint32_t ah[4], al[4];
            uint32_t ao = sw128(aRow * 64 + ks * 32 + aK16);
            ldsm_x4(ah, aH + ao);
            ldsm_x4(al, aL + ao);
            #pragma unroll
            for (int np = 0; np < 6; ++np) {
                uint32_t brow = np * 16 + bRowSel;
                uint32_t bo = sw128(brow * 64 + ks * 32 + bK16);
                uint32_t th[4], tl[4];
                ldsm_x4(th, wH + bo);
                ldsm_x4(tl, wL + bo);
                mma16816(acc[2 * np],     ah, th);
                mma16816(acc[2 * np],     ah, tl);
                mma16816(acc[2 * np],     al, th);
                mma16816(acc[2 * np + 1], ah, th + 2);
                mma16816(acc[2 * np + 1], ah, tl + 2);
                mma16816(acc[2 * np + 1], al, th + 2);
            }
            {
                uint32_t brow = 96 + (lane & 7);
                uint32_t bo = sw128(brow * 64 + ks * 32 + bK16);
                uint32_t bh2[2], bl2[2];
                ldsm_x2(bh2, wH + bo);
                ldsm_x2(bl2, wL + bo);
                mma16816(acc[12], ah, bh2);
                mma16816(acc[12], ah, bl2);
                mma16816(acc[12], al, bh2);
            }
        }
    }

    float* dst = g_part + (size_t)blk * 12800;
    #pragma unroll
    for (int nt = 0; nt < 13; ++nt)
        #pragma unroll
        for (int e = 0; e < 4; ++e) {
            int n = nt * 8 + 2 * (lane & 3) + (e & 1);
            if (n < 100) {
                int m = mBase + (lane >> 2) + (e >= 2 ? 8 : 0);
                dst[m * 100 + n] = acc[nt][e];
            }
        }
}

__global__ void k_fc_reduce(const float* __restrict__ fcb, float* __restrict__ out) {
    int idx = blockIdx.x * blockDim.x + threadIdx.x;
    if (idx >= NB * 100) return;
    int n = idx % 100;
    float s = fcb[n];
    for (int sb = 0; sb < FC_SLABS; ++sb) s += g_part[sb * 12800 + idx];
    out[idx] = s;
}

// ---------------------------------------------------------------------------
extern "C" void kernel_launch(void* const* d_in, const int* in_sizes, int n_in,
                              void* d_out, int out_size) {
    const float* x         = (const float*)d_in[0];
    const float* W1        = (const float*)d_in[1];
    const float* W2        = (const float*)d_in[2];
    const float* W3        = (const float*)d_in[3];
    const float* tri_w     = (const float*)d_in[4];
    const float* crelu_b   = (const float*)d_in[5];
    const float* sfm_alpha = (const float*)d_in[6];
    const float* fcw       = (const float*)d_in[7];
    const float* fcb       = (const float*)d_in[8];
    float* out = (float*)d_out;

    static int attr_done = 0;
    if (!attr_done) {
        cudaFuncSetAttribute(k_conv2, cudaFuncAttributeMaxDynamicSharedMemorySize, C2_DYN);
        cudaFuncSetAttribute(k_conv3, cudaFuncAttributeMaxDynamicSharedMemorySize, C3_DYN);
        attr_done = 1;
    }

    k_zero<<<(int)((sizeof(g_a1f) + sizeof(g_a2f)) / 16 + 255) / 256, 256>>>();
    k_prep<<<47520, 256>>>(W2, W3, fcw);
    k_wsq<<<144, 256>>>(W2, W3);
    k_layer1<<<dim3(NBT, 2), 256>>>(x, W1, tri_w, crelu_b, sfm_alpha);
    k_xsq2<<<NBT, 256>>>();
    k_conv2<<<dim3(NBT, 3), 512, C2_DYN>>>(tri_w, crelu_b, sfm_alpha);
    k_xsq3<<<NBT, 256>>>();
    k_conv3<<<dim3(NBT, 2), 384, C3_DYN>>>(tri_w, crelu_b);
    k_fc_mma<<<FC_SLABS, 256>>>();
    k_fc_reduce<<<(NB * 100 + 255) / 256, 256>>>(fcb, out);
}

// round 6
// speedup vs baseline: 4.7259x; 1.0935x over previous
#include <cuda_runtime.h>
#include <cuda_fp16.h>
#include <cstdint>

#define NB 128
#define NT 3
#define NBT (NB*NT)

// ---------------- scratch (zero-initialized at module load; padding cells
// are NEVER written by any kernel, so they remain zero across all replays) --
__device__ __align__(16) __half g_a1f[NBT * 832 * 64];    // padded 26x32, ch-last
__device__ __align__(16) __half g_a2f[NBT * 224 * 128];   // padded 14x16, ch-last
__device__ __align__(16) __half g_a3h[NB * 110592];
__device__ __align__(16) __half g_a3l[NB * 110592];
__device__ __align__(16) __half g_fwh[100 * 110592];
__device__ __align__(16) __half g_fwl[100 * 110592];
__device__ float g_xsq2[NBT * 576];
__device__ float g_xsq3[NBT * 144];
__device__ float g_wsq2[NT * 128];
__device__ float g_wsq3[NT * 256];
__device__ __align__(16) __half g_w2f[27 * 8192];
__device__ __align__(16) __half g_w3f[54 * 16384];

#define FC_SLABS 216
#define FC_SLAB_K 512
__device__ float g_part[FC_SLABS * NB * 100];

// ---------------- helpers ----------------
static __device__ __forceinline__ uint32_t smem_u32(const void* p) {
    uint32_t a;
    asm("{ .reg .u64 t; cvta.to.shared.u64 t, %1; cvt.u32.u64 %0, t; }" : "=r"(a) : "l"(p));
    return a;
}
static __device__ __forceinline__ uint32_t sw128(uint32_t off) {
    return off ^ ((off >> 3) & 0x70);
}
static __device__ __forceinline__ void ldsm_x4(uint32_t* r, uint32_t addr) {
    asm volatile("ldmatrix.sync.aligned.m8n8.x4.shared.b16 {%0,%1,%2,%3}, [%4];"
                 : "=r"(r[0]), "=r"(r[1]), "=r"(r[2]), "=r"(r[3]) : "r"(addr));
}
static __device__ __forceinline__ void ldsm_x2(uint32_t* r, uint32_t addr) {
    asm volatile("ldmatrix.sync.aligned.m8n8.x2.shared.b16 {%0,%1}, [%2];"
                 : "=r"(r[0]), "=r"(r[1]) : "r"(addr));
}
static __device__ __forceinline__ void mma16816(float* d, const uint32_t* a, const uint32_t* b) {
    asm volatile("mma.sync.aligned.m16n8k16.row.col.f32.f16.f16.f32 "
                 "{%0,%1,%2,%3}, {%4,%5,%6,%7}, {%8,%9}, {%0,%1,%2,%3};"
                 : "+f"(d[0]), "+f"(d[1]), "+f"(d[2]), "+f"(d[3])
                 : "r"(a[0]), "r"(a[1]), "r"(a[2]), "r"(a[3]), "r"(b[0]), "r"(b[1]));
}

// ---------------- prep: swizzled weight images + fc hi/lo split ----------------
__global__ void k_prep(const float* __restrict__ W2, const float* __restrict__ W3,
                       const float* __restrict__ fcw) {
    int e = blockIdx.x * blockDim.x + threadIdx.x;
    if (e < 221184) {                         // t, tap, oc(128), k(64)
        int k = e & 63, oc = (e >> 6) & 127;
        int tap = (e >> 13) % 9, t = e / (9 * 8192);
        float w = W2[(t * 128 + oc) * 576 + k * 9 + tap];
        uint32_t sw = sw128((uint32_t)(oc * 128 + k * 2));
        *(__half*)((char*)(g_w2f + (size_t)(t * 9 + tap) * 8192) + sw) = __float2half(w);
    } else if (e < 1105920) {                 // t, half, tap, oc(128), k(128)
        int e2 = e - 221184;
        int k = e2 & 127, oc = (e2 >> 7) & 127;
        int tap = (e2 >> 14) % 9, th = e2 / (9 * 16384);
        int t = th >> 1, half = th & 1;
        float w = W3[(t * 256 + half * 128 + oc) * 1152 + k * 9 + tap];
        uint32_t off = (uint32_t)((k >> 6) * 16384) + sw128((uint32_t)(oc * 128 + (k & 63) * 2));
        *(__half*)((char*)(g_w3f + (size_t)(th * 9 + tap) * 16384) + off) = __float2half(w);
    } else if (e < 1105920 + 2764800) {       // fc weight hi/lo split (4/thread)
        int e2 = e - 1105920;
        float4 w = ((const float4*)fcw)[e2];
        __half h0 = __float2half(w.x), h1 = __float2half(w.y);
        __half h2 = __float2half(w.z), h3 = __float2half(w.w);
        __half l0 = __float2half(w.x - __half2float(h0));
        __half l1 = __float2half(w.y - __half2float(h1));
        __half l2 = __float2half(w.z - __half2float(h2));
        __half l3 = __float2half(w.w - __half2float(h3));
        ((__half2*)g_fwh)[e2 * 2]     = __halves2half2(h0, h1);
        ((__half2*)g_fwh)[e2 * 2 + 1] = __halves2half2(h2, h3);
        ((__half2*)g_fwl)[e2 * 2]     = __halves2half2(l0, l1);
        ((__half2*)g_fwl)[e2 * 2 + 1] = __halves2half2(l2, l3);
    }
}

// wsq: one warp per output channel, shfl reduce
__global__ void __launch_bounds__(256) k_wsq(const float* __restrict__ W2,
                                             const float* __restrict__ W3) {
    int oid = blockIdx.x * 8 + (threadIdx.x >> 5);
    int lane = threadIdx.x & 31;
    float s = 0.f;
    if (oid < NT * 128) {
        const float* p = W2 + oid * 576;
        for (int k = lane; k < 576; k += 32) {
            float w = __half2float(__float2half(p[k])); s += w * w;
        }
    } else {
        const float* p = W3 + (oid - NT * 128) * 1152;
        for (int k = lane; k < 1152; k += 32) {
            float w = __half2float(__float2half(p[k])); s += w * w;
        }
    }
    #pragma unroll
    for (int d = 16; d > 0; d >>= 1) s += __shfl_xor_sync(0xffffffffu, s, d);
    if (lane == 0) {
        if (oid < NT * 128) g_wsq2[oid] = s;
        else g_wsq3[oid - NT * 128] = s;
    }
}

// ---------------- layer 1: fp32 SIMT, y-split, 2 pooled outputs/iter ----------
__global__ void __launch_bounds__(256) k_layer1(
    const float* __restrict__ x, const float* __restrict__ W1,
    const float* __restrict__ tri_w, const float* __restrict__ crelu_b,
    const float* __restrict__ sfm_alpha)
{
    __shared__ __align__(16) float xpadL[28 * 52];
    __shared__ float xsqL[24 * 48];
    __shared__ float w1s[64 * 25];
    __shared__ float wsq1s[64];

    const int bt = blockIdx.x, t = bt % NT, h = blockIdx.y, tid = threadIdx.x;

    for (int idx = tid; idx < 28 * 52; idx += 256) {
        int r = idx / 52, c = idx % 52;
        int gr = h * 24 + r - 2, gc = c - 2;
        xpadL[idx] = (gr >= 0 && gr < 48 && gc >= 0 && gc < 48)
                   ? x[bt * 2304 + gr * 48 + gc] : 0.f;
    }
    for (int idx = tid; idx < 1600; idx += 256) w1s[idx] = W1[t * 1600 + idx];
    __syncthreads();

    if (tid < 64) {
        float s = 0.f;
        #pragma unroll
        for (int k = 0; k < 25; ++k) { float w = w1s[tid * 25 + k]; s += w * w; }
        wsq1s[tid] = s;
    }
    for (int idx = tid; idx < 24 * 48; idx += 256) {
        int y = idx / 48, xx = idx % 48;
        float s = 0.f;
        #pragma unroll
        for (int ky = 0; ky < 5; ++ky)
            #pragma unroll
            for (int kx = 0; kx < 5; ++kx) {
                float v = xpadL[(y + ky) * 52 + xx + kx];
                s += v * v;
            }
        xsqL[idx] = s;
    }
    __syncthreads();

    const int o = tid >> 2, sub = tid & 3;
    float wr[25];
    #pragma unroll
    for (int k = 0; k < 25; ++k) wr[k] = w1s[o * 25 + k];
    const float wq = wsq1s[o];
    const float tw = tri_w[t * 3 + 0], inv_tw = 1.f / tw;
    const float cb = crelu_b[t * 3 + 0];
    const float al = sfm_alpha[t * 2 + 0];
    const float c00 = al * al * al * 0.25f, c01 = al * al * 0.25f;
    const float c10 = al * 0.25f, c11 = 0.25f;

    for (int it = 0; it < 36; ++it) {
        int p = it * 4 + sub;                  // 144 horizontal pooled-pairs
        int pi = p / 12, pj = (p % 12) * 2;
        float pt[6][8];
        #pragma unroll
        for (int r = 0; r < 6; ++r) {
            const float* row = &xpadL[(2 * pi + r) * 52 + 2 * pj];
            #pragma unroll
            for (int s2 = 0; s2 < 4; ++s2) {
                float2 u = *(const float2*)(row + 2 * s2);
                pt[r][2 * s2] = u.x; pt[r][2 * s2 + 1] = u.y;
            }
        }
        float vv[2][4];
        #pragma unroll
        for (int a = 0; a < 2; ++a)
            #pragma unroll
            for (int b2 = 0; b2 < 4; ++b2) {
                float cr = 0.f;
                #pragma unroll
                for (int ky = 0; ky < 5; ++ky)
                    #pragma unroll
                    for (int kx = 0; kx < 5; ++kx)
                        cr += wr[ky * 5 + kx] * pt[a + ky][b2 + kx];
                float d = xsqL[(2 * pi + a) * 48 + 2 * pj + b2] - 2.f * cr + wq;
                d = fmaxf(d, 0.f);
                float v = 1.f - fminf(d, tw) * inv_tw;
                vv[a][b2] = (v >= cb) ? v : 0.f;
            }
        float pool0 = c00 * vv[0][0] + c01 * vv[0][1] + c10 * vv[1][0] + c11 * vv[1][1];
        float pool1 = c00 * vv[0][2] + c01 * vv[0][3] + c10 * vv[1][2] + c11 * vv[1][3];
        int gi = h * 12 + pi;
        size_t cell = ((size_t)bt * 832 + (gi + 1) * 32 + (pj + 1)) * 64 + o;
        g_a1f[cell] = __float2half(pool0);
        g_a1f[cell + 64] = __float2half(pool1);
    }
}

// ---------------- xsq maps ----------------
__global__ void __launch_bounds__(256) k_xsq2() {
    __shared__ float spad[26 * 26];
    const int bt = blockIdx.x, tid = threadIdx.x;
    for (int i = tid; i < 676; i += 256) spad[i] = 0.f;
    __syncthreads();
    for (int p = tid; p < 576; p += 256) {
        int y = p / 24, x = p % 24;
        const __half2* hp = (const __half2*)(g_a1f + ((size_t)bt * 832 + (y + 1) * 32 + x + 1) * 64);
        float acc = 0.f;
        #pragma unroll
        for (int c = 0; c < 32; ++c) {
            float2 f = __half22float2(hp[c]);
            acc += f.x * f.x + f.y * f.y;
        }
        spad[(y + 1) * 26 + (x + 1)] = acc;
    }
    __syncthreads();
    for (int p = tid; p < 576; p += 256) {
        int y = p / 24, x = p % 24;
        float acc = 0.f;
        #pragma unroll
        for (int r = 0; r < 3; ++r)
            #pragma unroll
            for (int cx = 0; cx < 3; ++cx)
                acc += spad[(y + r) * 26 + x + cx];
        g_xsq2[bt * 576 + p] = acc;
    }
}

__global__ void __launch_bounds__(256) k_xsq3() {
    __shared__ float spad[14 * 14];
    const int bt = blockIdx.x, tid = threadIdx.x;
    for (int i = tid; i < 196; i += 256) spad[i] = 0.f;
    __syncthreads();
    if (tid < 144) {
        int y = tid / 12, x = tid % 12;
        const __half2* hp = (const __half2*)(g_a2f + ((size_t)bt * 224 + (y + 1) * 16 + x + 1) * 128);
        float acc = 0.f;
        #pragma unroll
        for (int c = 0; c < 64; ++c) {
            float2 f = __half22float2(hp[c]);
            acc += f.x * f.x + f.y * f.y;
        }
        spad[(y + 1) * 14 + (x + 1)] = acc;
    }
    __syncthreads();
    if (tid < 144) {
        int y = tid / 12, x = tid % 12;
        float acc = 0.f;
        #pragma unroll
        for (int r = 0; r < 3; ++r)
            #pragma unroll
            for (int cx = 0; cx < 3; ++cx)
                acc += spad[(y + r) * 14 + x + cx];
        g_xsq3[bt * 144 + tid] = acc;
    }
}

// ---------------- conv2: implicit GEMM, double-buffered W ----------------
#define C2_AB 40960
#define C2_DYN 99840

__global__ void __launch_bounds__(512) k_conv2(
    const float* __restrict__ tri_w, const float* __restrict__ crelu_b,
    const float* __restrict__ sfm_alpha)
{
    extern __shared__ __align__(1024) unsigned char sm[];
    __shared__ uint32_t lutS[192];
    __shared__ float xsqS[192];
    __shared__ float wsqS[128];

    const int bt = blockIdx.x, t = bt % NT, ytile = blockIdx.y;
    const int y0 = ytile * 8;
    const int tid = threadIdx.x, wid = tid >> 5, lane = tid & 31;
    const uint32_t aBase = smem_u32(sm);
    const uint32_t wBase = aBase + C2_AB;

    {   // stage A: padded rows y0..y0+9 (320 cells)
        const uint4* src = (const uint4*)(g_a1f + ((size_t)bt * 832 + y0 * 32) * 64);
        #pragma unroll
        for (int u = 0; u < 5; ++u) {
            int idx = tid + u * 512;
            uint32_t off = sw128((uint32_t)((idx >> 3) * 128 + (idx & 7) * 16));
            *(uint4*)(sm + off) = src[idx];
        }
    }
    {   // stage W tap 0 into buf 0
        const uint4* wsrc = (const uint4*)(g_w2f + (size_t)(t * 9) * 8192);
        uint4* wdst = (uint4*)(sm + C2_AB);
        wdst[tid] = wsrc[tid];
        wdst[tid + 512] = wsrc[tid + 512];
    }
    if (tid < 192) {
        int r = tid / 24, c = tid % 24;
        lutS[tid] = (uint32_t)((r * 32 + c) * 128);
        xsqS[tid] = g_xsq2[bt * 576 + y0 * 24 + tid];
    }
    if (tid < 128) wsqS[tid] = g_wsq2[t * 128 + tid];

    const int wm = wid >> 2, wn = wid & 3;
    const int pBase = wm * 48, nBase = wn * 32;
    const int l15 = lane & 15;
    const uint32_t aKoff = ((lane >> 4) & 1) * 16;
    const uint32_t bRowK = (uint32_t)((nBase + (l15 & 7)) * 128 + ((l15 >> 3) & 1) * 16);

    float acc[3][4][4];
    #pragma unroll
    for (int mt = 0; mt < 3; ++mt)
        #pragma unroll
        for (int nt = 0; nt < 4; ++nt)
            #pragma unroll
            for (int e = 0; e < 4; ++e) acc[mt][nt][e] = 0.f;

    __syncthreads();
    uint32_t lutv[3];
    #pragma unroll
    for (int mt = 0; mt < 3; ++mt)
        lutv[mt] = lutS[pBase + mt * 16 + (lane & 7) + ((lane >> 3) & 1) * 8];

    for (int tap = 0; tap < 9; ++tap) {
        if (tap < 8) {   // prefetch next tap into other buffer
            const uint4* wsrc = (const uint4*)(g_w2f + (size_t)(t * 9 + tap + 1) * 8192);
            uint4* wdst = (uint4*)(sm + C2_AB + (((tap + 1) & 1) << 14));
            wdst[tid] = wsrc[tid];
            wdst[tid + 512] = wsrc[tid + 512];
        }
        const uint32_t wb = wBase + ((tap & 1) << 14);
        const uint32_t tapOff = (uint32_t)(((tap / 3) * 32 + (tap % 3)) * 128);
        #pragma unroll
        for (int ks = 0; ks < 4; ++ks) {
            const uint32_t kb = ks * 32;
            uint32_t a[3][4], b[4][2];
            #pragma unroll
            for (int mt = 0; mt < 3; ++mt)
                ldsm_x4(a[mt], aBase + sw128(lutv[mt] + tapOff + kb + aKoff));
            #pragma unroll
            for (int nt = 0; nt < 4; ++nt)
                ldsm_x2(b[nt], wb + sw128(bRowK + nt * 1024 + kb));
            #pragma unroll
            for (int mt = 0; mt < 3; ++mt)
                #pragma unroll
                for (int nt = 0; nt < 4; ++nt)
                    mma16816(acc[mt][nt], a[mt], b[nt]);
        }
        __syncthreads();
    }

    const float tw = tri_w[t * 3 + 1], inv_tw = 1.f / tw;
    const float cb = crelu_b[t * 3 + 1];
    const float al = sfm_alpha[t * 2 + 1];
    const float c00 = al * al * al * 0.25f, c01 = al * al * 0.25f;
    const float c10 = al * 0.25f, c11 = 0.25f;
    float* vbuf = (float*)sm;   // [192][130]

    #pragma unroll
    for (int mt = 0; mt < 3; ++mt)
        #pragma unroll
        for (int nt = 0; nt < 4; ++nt)
            #pragma unroll
            for (int e = 0; e < 4; ++e) {
                int p = pBase + mt * 16 + (lane >> 2) + (e >= 2 ? 8 : 0);
                int oc = nBase + nt * 8 + 2 * (lane & 3) + (e & 1);
                float d = fmaxf(xsqS[p] - 2.f * acc[mt][nt][e] + wsqS[oc], 0.f);
                float v = 1.f - fminf(d, tw) * inv_tw;
                vbuf[p * 130 + oc] = (v >= cb) ? v : 0.f;
            }
    __syncthreads();

    #pragma unroll
    for (int u = 0; u < 12; ++u) {
        int idx = tid + u * 512;
        int oc = idx & 127, q = idx >> 7;
        int pr = q / 12, pc = q % 12;
        int p00 = (2 * pr) * 24 + 2 * pc;
        float pooled = c00 * vbuf[p00 * 130 + oc] + c01 * vbuf[(p00 + 1) * 130 + oc]
                     + c10 * vbuf[(p00 + 24) * 130 + oc] + c11 * vbuf[(p00 + 25) * 130 + oc];
        int gi = ytile * 4 + pr;
        g_a2f[((size_t)bt * 224 + (gi + 1) * 16 + (pc + 1)) * 128 + oc] = __float2half(pooled);
    }
}

// ---------------- conv3: implicit GEMM, double-buffered W planes ----------------
#define C3_AP 28672
#define C3_WB 57344
#define C3_DYN 90112

__global__ void __launch_bounds__(384) k_conv3(
    const float* __restrict__ tri_w, const float* __restrict__ crelu_b)
{
    extern __shared__ __align__(1024) unsigned char sm[];
    __shared__ uint32_t lutS[144];
    __shared__ float xsqS[144];
    __shared__ float wsqS[128];

    const int bt = blockIdx.x, t = bt % NT, b = bt / NT;
    const int half = blockIdx.y;
    const int tid = threadIdx.x, wid = tid >> 5, lane = tid & 31;
    const uint32_t aBase = smem_u32(sm);
    const uint32_t wBase = aBase + C3_WB;
    const size_t wImgBase = (size_t)((t * 2 + half) * 9) * 2048;   // uint4 units

    {   // stage A: 224 cells x 256B, 2 k-planes
        const uint4* src = (const uint4*)(g_a2f + (size_t)bt * 224 * 128);
        for (int idx = tid; idx < 3584; idx += 384) {
            int cell = idx >> 4, chunk = idx & 15;
            uint32_t off = (uint32_t)((chunk >> 3) * C3_AP)
                         + sw128((uint32_t)(cell * 128 + (chunk & 7) * 16));
            *(uint4*)(sm + off) = src[idx];
        }
    }
    {   // stage W step 0 (tap 0, plane 0) into buf 0
        const uint4* wsrc = (const uint4*)g_w3f + wImgBase;
        uint4* wdst = (uint4*)(sm + C3_WB);
        for (int i = tid; i < 1024; i += 384) wdst[i] = wsrc[i];
    }
    if (tid < 144) {
        int r = tid / 12, c = tid % 12;
        lutS[tid] = (uint32_t)((r * 16 + c) * 128);
        xsqS[tid] = g_xsq3[bt * 144 + tid];
    }
    if (tid < 128) wsqS[tid] = g_wsq3[t * 256 + half * 128 + tid];

    const int wm = wid >> 2, wn = wid & 3;
    const int pBase = wm * 48, nBase = wn * 32;
    const int l15 = lane & 15;
    const uint32_t aKoff = ((lane >> 4) & 1) * 16;
    const uint32_t bRowK = (uint32_t)((nBase + (l15 & 7)) * 128 + ((l15 >> 3) & 1) * 16);

    float acc[3][4][4];
    #pragma unroll
    for (int mt = 0; mt < 3; ++mt)
        #pragma unroll
        for (int nt = 0; nt < 4; ++nt)
            #pragma unroll
            for (int e = 0; e < 4; ++e) acc[mt][nt][e] = 0.f;

    __syncthreads();
    uint32_t lutv[3];
    #pragma unroll
    for (int mt = 0; mt < 3; ++mt)
        lutv[mt] = lutS[pBase + mt * 16 + (lane & 7) + ((lane >> 3) & 1) * 8];

    for (int s = 0; s < 18; ++s) {             // (tap, plane) steps
        if (s < 17) {                          // prefetch next step
            int s1 = s + 1, tap1 = s1 >> 1, pl1 = s1 & 1;
            const uint4* wsrc = (const uint4*)g_w3f + wImgBase + tap1 * 2048 + pl1 * 1024;
            uint4* wdst = (uint4*)(sm + C3_WB + ((s1 & 1) << 14));
            for (int i = tid; i < 1024; i += 384) wdst[i] = wsrc[i];
        }
        const int tap = s >> 1, pl = s & 1;
        const uint32_t aplane = pl ? (uint32_t)C3_AP : 0u;
        const uint32_t wb = wBase + ((s & 1) << 14);
        const uint32_t tapOff = (uint32_t)(((tap / 3) * 16 + (tap % 3)) * 128);
        #pragma unroll
        for (int ks = 0; ks < 4; ++ks) {
            const uint32_t kb = ks * 32;
            uint32_t a[3][4], b[4][2];
            #pragma unroll
            for (int mt = 0; mt < 3; ++mt)
                ldsm_x4(a[mt], aBase + aplane + sw128(lutv[mt] + tapOff + kb + aKoff));
            #pragma unroll
            for (int nt = 0; nt < 4; ++nt)
                ldsm_x2(b[nt], wb + sw128(bRowK + nt * 1024 + kb));
            #pragma unroll
            for (int mt = 0; mt < 3; ++mt)
                #pragma unroll
                for (int nt = 0; nt < 4; ++nt)
                    mma16816(acc[mt][nt], a[mt], b[nt]);
        }
        __syncthreads();
    }

    // epilogue: hi/lo split staged via smem for coalesced global stores
    const float tw = tri_w[t * 3 + 2], inv_tw = 1.f / tw;
    const float cb = crelu_b[t * 3 + 2];
    __half2* sOut = (__half2*)sm;    // [128][144] half2 = 73728 B (MMA done)

    #pragma unroll
    for (int mt = 0; mt < 3; ++mt)
        #pragma unroll
        for (int nt = 0; nt < 4; ++nt)
            #pragma unroll
            for (int e = 0; e < 4; ++e) {
                int p = pBase + mt * 16 + (lane >> 2) + (e >= 2 ? 8 : 0);
                int oc = nBase + nt * 8 + 2 * (lane & 3) + (e & 1);
                float d = fmaxf(xsqS[p] - 2.f * acc[mt][nt][e] + wsqS[oc], 0.f);
                float v = 1.f - fminf(d, tw) * inv_tw;
                v = (v >= cb) ? v : 0.f;
                __half hi = __float2half(v);
                __half lo = __float2half(v - __half2float(hi));
                sOut[oc * 144 + p] = __halves2half2(hi, lo);
            }
    __syncthreads();
    size_t base = (size_t)b * 110592 + t * 36864 + half * 18432;
    for (int idx = tid; idx < 18432; idx += 384) {
        __half2 hv = sOut[idx];
        g_a3h[base + idx] = __low2half(hv);
        g_a3l[base + idx] = __high2half(hv);
    }
}

// ---------------- FC: fp16 mma, 3-pass hi/lo, split-K ----------------
__global__ void __launch_bounds__(256) k_fc_mma() {
    __shared__ __align__(16) unsigned char aHs[8192];
    __shared__ __align__(16) unsigned char aLs[8192];
    __shared__ __align__(16) unsigned char wHs[6656];
    __shared__ __align__(16) unsigned char wLs[6656];

    const int blk = blockIdx.x, tid = threadIdx.x, wid = tid >> 5, lane = tid & 31;
    const int k0 = blk * FC_SLAB_K;
    const uint32_t aH = smem_u32(aHs), aL = smem_u32(aLs);
    const uint32_t wH = smem_u32(wHs), wL = smem_u32(wLs);

    float acc[13][4];
    #pragma unroll
    for (int nt = 0; nt < 13; ++nt)
        #pragma unroll
        for (int e = 0; e < 4; ++e) acc[nt][e] = 0.f;

    const int mBase = wid * 16;
    const uint32_t aRow = (uint32_t)(mBase + (lane & 7) + ((lane >> 3) & 1) * 8);
    const uint32_t aK16 = ((lane >> 4) & 1) * 16;
    const uint32_t bK16 = ((lane >> 3) & 1) * 16;
    const uint32_t bRowSel = ((lane >> 4) & 1) * 8 + (lane & 7);

    for (int ch = 0; ch < 16; ++ch) {
        int kb = k0 + ch * 32;
        __syncthreads();
        for (int idx = tid; idx < 512; idx += 256) {
            int r = idx >> 2, c = idx & 3;
            uint32_t sw = sw128((uint32_t)(r * 64 + c * 16));
            *(uint4*)(aHs + sw) = *(const uint4*)(g_a3h + (size_t)r * 110592 + kb + c * 8);
            *(uint4*)(aLs + sw) = *(const uint4*)(g_a3l + (size_t)r * 110592 + kb + c * 8);
        }
        for (int idx = tid; idx < 416; idx += 256) {
            int r = idx >> 2, c = idx & 3;
            uint32_t sw = sw128((uint32_t)(r * 64 + c * 16));
            uint4 vh = {0u, 0u, 0u, 0u}, vl = {0u, 0u, 0u, 0u};
            if (r < 100) {
                vh = *(const uint4*)(g_fwh + (size_t)r * 110592 + kb + c * 8);
                vl = *(const uint4*)(g_fwl + (size_t)r * 110592 + kb + c * 8);
            }
            *(uint4*)(wHs + sw) = vh;
            *(uint4*)(wLs + sw) = vl;
        }
        __syncthreads();

        #pragma unroll
        for (int ks = 0; ks < 2; ++ks) {
            uint32_t ah[4], al[4];
            uint32_t ao = sw128(aRow * 64 + ks * 32 + aK16);
            ldsm_x4(ah, aH + ao);
            ldsm_x4(al, aL + ao);
            #pragma unroll
            for (int np = 0; np < 6; ++np) {
                uint32_t brow = np * 16 + bRowSel;
                uint32_t bo = sw128(brow * 64 + ks * 32 + bK16);
                uint32_t th[4], tl[4];
                ldsm_x4(th, wH + bo);
                ldsm_x4(tl, wL + bo);
                mma16816(acc[2 * np],     ah, th);
                mma16816(acc[2 * np],     ah, tl);
                mma16816(acc[2 * np],     al, th);
                mma16816(acc[2 * np + 1], ah, th + 2);
                mma16816(acc[2 * np + 1], ah, tl + 2);
                mma16816(acc[2 * np + 1], al, th + 2);
            }
            {
                uint32_t brow = 96 + (lane & 7);
                uint32_t bo = sw128(brow * 64 + ks * 32 + bK16);
                uint32_t bh2[2], bl2[2];
                ldsm_x2(bh2, wH + bo);
                ldsm_x2(bl2, wL + bo);
                mma16816(acc[12], ah, bh2);
                mma16816(acc[12], ah, bl2);
                mma16816(acc[12], al, bh2);
            }
        }
    }

    float* dst = g_part + (size_t)blk * 12800;
    #pragma unroll
    for (int nt = 0; nt < 13; ++nt)
        #pragma unroll
        for (int e = 0; e < 4; ++e) {
            int n = nt * 8 + 2 * (lane & 3) + (e & 1);
            if (n < 100) {
                int m = mBase + (lane >> 2) + (e >= 2 ? 8 : 0);
                dst[m * 100 + n] = acc[nt][e];
            }
        }
}

__global__ void k_fc_reduce(const float* __restrict__ fcb, float* __restrict__ out) {
    int idx = blockIdx.x * blockDim.x + threadIdx.x;
    if (idx >= NB * 100) return;
    int n = idx % 100;
    float s0 = fcb[n], s1 = 0.f, s2 = 0.f, s3 = 0.f;
    #pragma unroll 4
    for (int sb = 0; sb < FC_SLABS; sb += 4) {
        s0 += g_part[(sb + 0) * 12800 + idx];
        s1 += g_part[(sb + 1) * 12800 + idx];
        s2 += g_part[(sb + 2) * 12800 + idx];
        s3 += g_part[(sb + 3) * 12800 + idx];
    }
    out[idx] = (s0 + s1) + (s2 + s3);
}

// ---------------------------------------------------------------------------
extern "C" void kernel_launch(void* const* d_in, const int* in_sizes, int n_in,
                              void* d_out, int out_size) {
    const float* x         = (const float*)d_in[0];
    const float* W1        = (const float*)d_in[1];
    const float* W2        = (const float*)d_in[2];
    const float* W3        = (const float*)d_in[3];
    const float* tri_w     = (const float*)d_in[4];
    const float* crelu_b   = (const float*)d_in[5];
    const float* sfm_alpha = (const float*)d_in[6];
    const float* fcw       = (const float*)d_in[7];
    const float* fcb       = (const float*)d_in[8];
    float* out = (float*)d_out;

    static int attr_done = 0;
    if (!attr_done) {
        cudaFuncSetAttribute(k_conv2, cudaFuncAttributeMaxDynamicSharedMemorySize, C2_DYN);
        cudaFuncSetAttribute(k_conv3, cudaFuncAttributeMaxDynamicSharedMemorySize, C3_DYN);
        attr_done = 1;
    }

    k_prep<<<15120, 256>>>(W2, W3, fcw);
    k_wsq<<<144, 256>>>(W2, W3);
    k_layer1<<<dim3(NBT, 2), 256>>>(x, W1, tri_w, crelu_b, sfm_alpha);
    k_xsq2<<<NBT, 256>>>();
    k_conv2<<<dim3(NBT, 3), 512, C2_DYN>>>(tri_w, crelu_b, sfm_alpha);
    k_xsq3<<<NBT, 256>>>();
    k_conv3<<<dim3(NBT, 2), 384, C3_DYN>>>(tri_w, crelu_b);
    k_fc_mma<<<FC_SLABS, 256>>>();
    k_fc_reduce<<<(NB * 100 + 255) / 256, 256>>>(fcb, out);
}

// round 8
// speedup vs baseline: 5.4830x; 1.1602x over previous
#include <cuda_runtime.h>
#include <cuda_fp16.h>
#include <cstdint>

#define NB 128
#define NT 3
#define NBT (NB*NT)

// ---------------- scratch (zero-init at load; padding never written) -------
__device__ __align__(16) __half g_a1f[NBT * 832 * 64];    // padded 26x32, ch-last
__device__ __align__(16) __half g_a2f[NBT * 224 * 128];   // padded 14x16, ch-last
__device__ __align__(16) __half g_a3h[NB * 110592];
__device__ __align__(16) __half g_a3l[NB * 110592];
__device__ __align__(16) __half g_fwh[100 * 110592];
__device__ __align__(16) __half g_fwl[100 * 110592];
__device__ float g_wsq2[NT * 128];
__device__ float g_wsq3[NT * 256];
__device__ __align__(16) __half g_w2f[27 * 8192];
__device__ __align__(16) __half g_w3f[54 * 16384];

#define FC_SLABS 216
#define FC_SLAB_K 512
__device__ float g_part[FC_SLABS * NB * 100];

// ---------------- helpers ----------------
static __device__ __forceinline__ uint32_t smem_u32(const void* p) {
    uint32_t a;
    asm("{ .reg .u64 t; cvta.to.shared.u64 t, %1; cvt.u32.u64 %0, t; }" : "=r"(a) : "l"(p));
    return a;
}
static __device__ __forceinline__ uint32_t sw128(uint32_t off) {
    return off ^ ((off >> 3) & 0x70);
}
static __device__ __forceinline__ void cp16(uint32_t dst, const void* src) {
    asm volatile("cp.async.cg.shared.global [%0], [%1], 16;" :: "r"(dst), "l"(src) : "memory");
}
#define CP_COMMIT() asm volatile("cp.async.commit_group;" ::: "memory")
#define CP_WAIT0()  asm volatile("cp.async.wait_group 0;" ::: "memory")
static __device__ __forceinline__ void ldsm_x4(uint32_t* r, uint32_t addr) {
    asm volatile("ldmatrix.sync.aligned.m8n8.x4.shared.b16 {%0,%1,%2,%3}, [%4];"
                 : "=r"(r[0]), "=r"(r[1]), "=r"(r[2]), "=r"(r[3]) : "r"(addr));
}
static __device__ __forceinline__ void ldsm_x2(uint32_t* r, uint32_t addr) {
    asm volatile("ldmatrix.sync.aligned.m8n8.x2.shared.b16 {%0,%1}, [%2];"
                 : "=r"(r[0]), "=r"(r[1]) : "r"(addr));
}
static __device__ __forceinline__ void mma16816(float* d, const uint32_t* a, const uint32_t* b) {
    asm volatile("mma.sync.aligned.m16n8k16.row.col.f32.f16.f16.f32 "
                 "{%0,%1,%2,%3}, {%4,%5,%6,%7}, {%8,%9}, {%0,%1,%2,%3};"
                 : "+f"(d[0]), "+f"(d[1]), "+f"(d[2]), "+f"(d[3])
                 : "r"(a[0]), "r"(a[1]), "r"(a[2]), "r"(a[3]), "r"(b[0]), "r"(b[1]));
}

// ---------------- prep: swizzled weight images + fc hi/lo split ----------------
__global__ void k_prep(const float* __restrict__ W2, const float* __restrict__ W3,
                       const float* __restrict__ fcw) {
    int e = blockIdx.x * blockDim.x + threadIdx.x;
    if (e < 221184) {                         // t, tap, oc(128), k(64)
        int k = e & 63, oc = (e >> 6) & 127;
        int tap = (e >> 13) % 9, t = e / (9 * 8192);
        float w = W2[(t * 128 + oc) * 576 + k * 9 + tap];
        uint32_t sw = sw128((uint32_t)(oc * 128 + k * 2));
        *(__half*)((char*)(g_w2f + (size_t)(t * 9 + tap) * 8192) + sw) = __float2half(w);
    } else if (e < 1105920) {                 // t, half, tap, oc(128), k(128)
        int e2 = e - 221184;
        int k = e2 & 127, oc = (e2 >> 7) & 127;
        int tap = (e2 >> 14) % 9, th = e2 / (9 * 16384);
        int t = th >> 1, half = th & 1;
        float w = W3[(t * 256 + half * 128 + oc) * 1152 + k * 9 + tap];
        uint32_t off = (uint32_t)((k >> 6) * 16384) + sw128((uint32_t)(oc * 128 + (k & 63) * 2));
        *(__half*)((char*)(g_w3f + (size_t)(th * 9 + tap) * 16384) + off) = __float2half(w);
    } else if (e < 1105920 + 2764800) {       // fc weight hi/lo split (4/thread)
        int e2 = e - 1105920;
        float4 w = ((const float4*)fcw)[e2];
        __half h0 = __float2half(w.x), h1 = __float2half(w.y);
        __half h2 = __float2half(w.z), h3 = __float2half(w.w);
        __half l0 = __float2half(w.x - __half2float(h0));
        __half l1 = __float2half(w.y - __half2float(h1));
        __half l2 = __float2half(w.z - __half2float(h2));
        __half l3 = __float2half(w.w - __half2float(h3));
        ((__half2*)g_fwh)[e2 * 2]     = __halves2half2(h0, h1);
        ((__half2*)g_fwh)[e2 * 2 + 1] = __halves2half2(h2, h3);
        ((__half2*)g_fwl)[e2 * 2]     = __halves2half2(l0, l1);
        ((__half2*)g_fwl)[e2 * 2 + 1] = __halves2half2(l2, l3);
    }
}

// wsq: one warp per output channel, shfl reduce
__global__ void __launch_bounds__(256) k_wsq(const float* __restrict__ W2,
                                             const float* __restrict__ W3) {
    int oid = blockIdx.x * 8 + (threadIdx.x >> 5);
    int lane = threadIdx.x & 31;
    float s = 0.f;
    if (oid < NT * 128) {
        const float* p = W2 + oid * 576;
        for (int k = lane; k < 576; k += 32) {
            float w = __half2float(__float2half(p[k])); s += w * w;
        }
    } else {
        const float* p = W3 + (oid - NT * 128) * 1152;
        for (int k = lane; k < 1152; k += 32) {
            float w = __half2float(__float2half(p[k])); s += w * w;
        }
    }
    #pragma unroll
    for (int d = 16; d > 0; d >>= 1) s += __shfl_xor_sync(0xffffffffu, s, d);
    if (lane == 0) {
        if (oid < NT * 128) g_wsq2[oid] = s;
        else g_wsq3[oid - NT * 128] = s;
    }
}

// ---------------- layer 1: fp32 SIMT, y-split, 2 pooled outputs/iter ----------
__global__ void __launch_bounds__(256) k_layer1(
    const float* __restrict__ x, const float* __restrict__ W1,
    const float* __restrict__ tri_w, const float* __restrict__ crelu_b,
    const float* __restrict__ sfm_alpha)
{
    __shared__ __align__(16) float xpadL[28 * 52];
    __shared__ float xsqL[24 * 48];
    __shared__ float w1s[64 * 25];
    __shared__ float wsq1s[64];

    const int bt = blockIdx.x, t = bt % NT, h = blockIdx.y, tid = threadIdx.x;

    for (int idx = tid; idx < 28 * 52; idx += 256) {
        int r = idx / 52, c = idx % 52;
        int gr = h * 24 + r - 2, gc = c - 2;
        xpadL[idx] = (gr >= 0 && gr < 48 && gc >= 0 && gc < 48)
                   ? x[bt * 2304 + gr * 48 + gc] : 0.f;
    }
    for (int idx = tid; idx < 1600; idx += 256) w1s[idx] = W1[t * 1600 + idx];
    __syncthreads();

    if (tid < 64) {
        float s = 0.f;
        #pragma unroll
        for (int k = 0; k < 25; ++k) { float w = w1s[tid * 25 + k]; s += w * w; }
        wsq1s[tid] = s;
    }
    for (int idx = tid; idx < 24 * 48; idx += 256) {
        int y = idx / 48, xx = idx % 48;
        float s = 0.f;
        #pragma unroll
        for (int ky = 0; ky < 5; ++ky)
            #pragma unroll
            for (int kx = 0; kx < 5; ++kx) {
                float v = xpadL[(y + ky) * 52 + xx + kx];
                s += v * v;
            }
        xsqL[idx] = s;
    }
    __syncthreads();

    const int o = tid >> 2, sub = tid & 3;
    float wr[25];
    #pragma unroll
    for (int k = 0; k < 25; ++k) wr[k] = w1s[o * 25 + k];
    const float wq = wsq1s[o];
    const float tw = tri_w[t * 3 + 0], inv_tw = 1.f / tw;
    const float cb = crelu_b[t * 3 + 0];
    const float al = sfm_alpha[t * 2 + 0];
    const float c00 = al * al * al * 0.25f, c01 = al * al * 0.25f;
    const float c10 = al * 0.25f, c11 = 0.25f;

    for (int it = 0; it < 36; ++it) {
        int p = it * 4 + sub;
        int pi = p / 12, pj = (p % 12) * 2;
        float pt[6][8];
        #pragma unroll
        for (int r = 0; r < 6; ++r) {
            const float* row = &xpadL[(2 * pi + r) * 52 + 2 * pj];
            #pragma unroll
            for (int s2 = 0; s2 < 4; ++s2) {
                float2 u = *(const float2*)(row + 2 * s2);
                pt[r][2 * s2] = u.x; pt[r][2 * s2 + 1] = u.y;
            }
        }
        float vv[2][4];
        #pragma unroll
        for (int a = 0; a < 2; ++a)
            #pragma unroll
            for (int b2 = 0; b2 < 4; ++b2) {
                float cr = 0.f;
                #pragma unroll
                for (int ky = 0; ky < 5; ++ky)
                    #pragma unroll
                    for (int kx = 0; kx < 5; ++kx)
                        cr += wr[ky * 5 + kx] * pt[a + ky][b2 + kx];
                float d = xsqL[(2 * pi + a) * 48 + 2 * pj + b2] - 2.f * cr + wq;
                d = fmaxf(d, 0.f);
                float v = 1.f - fminf(d, tw) * inv_tw;
                vv[a][b2] = (v >= cb) ? v : 0.f;
            }
        float pool0 = c00 * vv[0][0] + c01 * vv[0][1] + c10 * vv[1][0] + c11 * vv[1][1];
        float pool1 = c00 * vv[0][2] + c01 * vv[0][3] + c10 * vv[1][2] + c11 * vv[1][3];
        int gi = h * 12 + pi;
        size_t cell = ((size_t)bt * 832 + (gi + 1) * 32 + (pj + 1)) * 64 + o;
        g_a1f[cell] = __float2half(pool0);
        g_a1f[cell + 64] = __float2half(pool1);
    }
}

// ---------------- conv2: implicit GEMM, fused xsq, cp.async W prefetch -------
#define C2_AB 40960
#define C2_DYN 99840

__global__ void __launch_bounds__(512) k_conv2(
    const float* __restrict__ tri_w, const float* __restrict__ crelu_b,
    const float* __restrict__ sfm_alpha)
{
    extern __shared__ __align__(1024) unsigned char sm[];
    __shared__ uint32_t lutS[192];
    __shared__ float xsqS[192];
    __shared__ float wsqS[128];
    __shared__ float cellsq[320];

    const int bt = blockIdx.x, t = bt % NT, ytile = blockIdx.y;
    const int y0 = ytile * 8;
    const int tid = threadIdx.x, wid = tid >> 5, lane = tid & 31;
    const uint32_t aBase = smem_u32(sm);
    const uint32_t wBase = aBase + C2_AB;

    {   // stage A: padded rows y0..y0+9 (320 cells)
        const uint4* src = (const uint4*)(g_a1f + ((size_t)bt * 832 + y0 * 32) * 64);
        #pragma unroll
        for (int u = 0; u < 5; ++u) {
            int idx = tid + u * 512;
            uint32_t off = sw128((uint32_t)((idx >> 3) * 128 + (idx & 7) * 16));
            *(uint4*)(sm + off) = src[idx];
        }
    }
    {   // stage W tap 0 into buf 0
        const uint4* wsrc = (const uint4*)(g_w2f + (size_t)(t * 9) * 8192);
        uint4* wdst = (uint4*)(sm + C2_AB);
        wdst[tid] = wsrc[tid];
        wdst[tid + 512] = wsrc[tid + 512];
    }
    if (tid < 192) {
        int r = tid / 24, c = tid % 24;
        lutS[tid] = (uint32_t)((r * 32 + c) * 128);
    }
    if (tid < 128) wsqS[tid] = g_wsq2[t * 128 + tid];
    __syncthreads();

    // fused xsq: per-cell channel sumsq (swizzle-invariant row sum)
    if (tid < 320) {
        float s = 0.f;
        #pragma unroll
        for (int ch = 0; ch < 8; ++ch) {
            uint4 v = *(const uint4*)(sm + sw128((uint32_t)(tid * 128 + ch * 16)));
            const __half2* hh = (const __half2*)&v;
            #pragma unroll
            for (int q = 0; q < 4; ++q) {
                float2 f = __half22float2(hh[q]);
                s += f.x * f.x + f.y * f.y;
            }
        }
        cellsq[tid] = s;
    }
    uint32_t lutv[3];
    const int wm = wid >> 2, wn = wid & 3;
    const int pBase = wm * 48, nBase = wn * 32;
    #pragma unroll
    for (int mt = 0; mt < 3; ++mt)
        lutv[mt] = lutS[pBase + mt * 16 + (lane & 7) + ((lane >> 3) & 1) * 8];
    __syncthreads();
    if (tid < 192) {
        int r = tid / 24, c = tid % 24;
        float s = 0.f;
        #pragma unroll
        for (int dr = 0; dr < 3; ++dr)
            #pragma unroll
            for (int dc = 0; dc < 3; ++dc)
                s += cellsq[(r + dr) * 32 + c + dc];
        xsqS[tid] = s;
    }

    const uint32_t aKoff = ((lane >> 4) & 1) * 16;
    const uint32_t bRow4 = (uint32_t)((nBase + ((lane >> 4) & 1) * 8 + (lane & 7)) * 128
                                      + ((lane >> 3) & 1) * 16);

    float acc[3][4][4];
    #pragma unroll
    for (int mt = 0; mt < 3; ++mt)
        #pragma unroll
        for (int nt = 0; nt < 4; ++nt)
            #pragma unroll
            for (int e = 0; e < 4; ++e) acc[mt][nt][e] = 0.f;

    for (int tap = 0; tap < 9; ++tap) {
        if (tap < 8) {   // cp.async prefetch next tap
            const char* wsrc = (const char*)(g_w2f + (size_t)(t * 9 + tap + 1) * 8192);
            uint32_t wdst = wBase + (((tap + 1) & 1) << 14);
            cp16(wdst + tid * 16, wsrc + tid * 16);
            cp16(wdst + (tid + 512) * 16, wsrc + (tid + 512) * 16);
            CP_COMMIT();
        }
        const uint32_t wb = wBase + ((tap & 1) << 14);
        const uint32_t tapOff = (uint32_t)(((tap / 3) * 32 + (tap % 3)) * 128);
        #pragma unroll
        for (int ks = 0; ks < 4; ++ks) {
            const uint32_t kb = ks * 32;
            uint32_t a[3][4], b4[2][4];
            #pragma unroll
            for (int mt = 0; mt < 3; ++mt)
                ldsm_x4(a[mt], aBase + sw128(lutv[mt] + tapOff + kb + aKoff));
            ldsm_x4(b4[0], wb + sw128(bRow4 + kb));
            ldsm_x4(b4[1], wb + sw128(bRow4 + kb + 2048));
            #pragma unroll
            for (int mt = 0; mt < 3; ++mt)
                #pragma unroll
                for (int p2 = 0; p2 < 2; ++p2)
                    #pragma unroll
                    for (int q = 0; q < 2; ++q)
                        mma16816(acc[mt][2 * p2 + q], a[mt], b4[p2] + 2 * q);
        }
        if (tap < 8) CP_WAIT0();
        __syncthreads();
    }

    const float tw = tri_w[t * 3 + 1], inv_tw = 1.f / tw;
    const float cb = crelu_b[t * 3 + 1];
    const float al = sfm_alpha[t * 2 + 1];
    const float c00 = al * al * al * 0.25f, c01 = al * al * 0.25f;
    const float c10 = al * 0.25f, c11 = 0.25f;
    float* vbuf = (float*)sm;   // [192][130]

    #pragma unroll
    for (int mt = 0; mt < 3; ++mt)
        #pragma unroll
        for (int nt = 0; nt < 4; ++nt)
            #pragma unroll
            for (int e = 0; e < 4; ++e) {
                int p = pBase + mt * 16 + (lane >> 2) + (e >= 2 ? 8 : 0);
                int oc = nBase + nt * 8 + 2 * (lane & 3) + (e & 1);
                float d = fmaxf(xsqS[p] - 2.f * acc[mt][nt][e] + wsqS[oc], 0.f);
                float v = 1.f - fminf(d, tw) * inv_tw;
                vbuf[p * 130 + oc] = (v >= cb) ? v : 0.f;
            }
    __syncthreads();

    #pragma unroll
    for (int u = 0; u < 12; ++u) {
        int idx = tid + u * 512;
        int oc = idx & 127, q = idx >> 7;
        int pr = q / 12, pc = q % 12;
        int p00 = (2 * pr) * 24 + 2 * pc;
        float pooled = c00 * vbuf[p00 * 130 + oc] + c01 * vbuf[(p00 + 1) * 130 + oc]
                     + c10 * vbuf[(p00 + 24) * 130 + oc] + c11 * vbuf[(p00 + 25) * 130 + oc];
        int gi = ytile * 4 + pr;
        g_a2f[((size_t)bt * 224 + (gi + 1) * 16 + (pc + 1)) * 128 + oc] = __float2half(pooled);
    }
}

// ---------------- conv3: implicit GEMM, fused xsq, cp.async W prefetch -------
#define C3_AP 28672
#define C3_WB 57344
#define C3_DYN 90112

__global__ void __launch_bounds__(384) k_conv3(
    const float* __restrict__ tri_w, const float* __restrict__ crelu_b)
{
    extern __shared__ __align__(1024) unsigned char sm[];
    __shared__ uint32_t lutS[144];
    __shared__ float xsqS3[144];
    __shared__ float wsqS[128];
    __shared__ float cellsq3[224];

    const int bt = blockIdx.x, t = bt % NT, b = bt / NT;
    const int half = blockIdx.y;
    const int tid = threadIdx.x, wid = tid >> 5, lane = tid & 31;
    const uint32_t aBase = smem_u32(sm);
    const uint32_t wBase = aBase + C3_WB;
    const uint4* wImg = (const uint4*)g_w3f + (size_t)((t * 2 + half) * 9) * 2048;

    {   // stage A: 224 cells x 256B, 2 k-planes
        const uint4* src = (const uint4*)(g_a2f + (size_t)bt * 224 * 128);
        for (int idx = tid; idx < 3584; idx += 384) {
            int cell = idx >> 4, chunk = idx & 15;
            uint32_t off = (uint32_t)((chunk >> 3) * C3_AP)
                         + sw128((uint32_t)(cell * 128 + (chunk & 7) * 16));
            *(uint4*)(sm + off) = src[idx];
        }
    }
    {   // stage W step 0
        uint4* wdst = (uint4*)(sm + C3_WB);
        for (int i = tid; i < 1024; i += 384) wdst[i] = wImg[i];
    }
    if (tid < 144) {
        int r = tid / 12, c = tid % 12;
        lutS[tid] = (uint32_t)((r * 16 + c) * 128);
    }
    if (tid < 128) wsqS[tid] = g_wsq3[t * 256 + half * 128 + tid];
    __syncthreads();

    // fused xsq3
    if (tid < 224) {
        float s = 0.f;
        #pragma unroll
        for (int pl = 0; pl < 2; ++pl)
            #pragma unroll
            for (int ch = 0; ch < 8; ++ch) {
                uint4 v = *(const uint4*)(sm + pl * C3_AP
                                          + sw128((uint32_t)(tid * 128 + ch * 16)));
                const __half2* hh = (const __half2*)&v;
                #pragma unroll
                for (int q = 0; q < 4; ++q) {
                    float2 f = __half22float2(hh[q]);
                    s += f.x * f.x + f.y * f.y;
                }
            }
        cellsq3[tid] = s;
    }
    uint32_t lutv[3];
    const int wm = wid >> 2, wn = wid & 3;
    const int pBase = wm * 48, nBase = wn * 32;
    #pragma unroll
    for (int mt = 0; mt < 3; ++mt)
        lutv[mt] = lutS[pBase + mt * 16 + (lane & 7) + ((lane >> 3) & 1) * 8];
    __syncthreads();
    if (tid < 144) {
        int r = tid / 12, c = tid % 12;
        float s = 0.f;
        #pragma unroll
        for (int dr = 0; dr < 3; ++dr)
            #pragma unroll
            for (int dc = 0; dc < 3; ++dc)
                s += cellsq3[(r + dr) * 16 + c + dc];
        xsqS3[tid] = s;
    }

    const uint32_t aKoff = ((lane >> 4) & 1) * 16;
    const uint32_t bRow4 = (uint32_t)((nBase + ((lane >> 4) & 1) * 8 + (lane & 7)) * 128
                                      + ((lane >> 3) & 1) * 16);

    float acc[3][4][4];
    #pragma unroll
    for (int mt = 0; mt < 3; ++mt)
        #pragma unroll
        for (int nt = 0; nt < 4; ++nt)
            #pragma unroll
            for (int e = 0; e < 4; ++e) acc[mt][nt][e] = 0.f;

    for (int s = 0; s < 18; ++s) {             // (tap, plane) steps
        if (s < 17) {                          // cp.async prefetch next step
            int s1 = s + 1;
            const char* wsrc = (const char*)(wImg + (s1 >> 1) * 2048 + (s1 & 1) * 1024);
            uint32_t wdst = wBase + ((s1 & 1) << 14);
            for (int i = tid; i < 1024; i += 384)
                cp16(wdst + i * 16, wsrc + i * 16);
            CP_COMMIT();
        }
        const int tap = s >> 1, pl = s & 1;
        const uint32_t aplane = pl ? (uint32_t)C3_AP : 0u;
        const uint32_t wb = wBase + ((s & 1) << 14);
        const uint32_t tapOff = (uint32_t)(((tap / 3) * 16 + (tap % 3)) * 128);
        #pragma unroll
        for (int ks = 0; ks < 4; ++ks) {
            const uint32_t kb = ks * 32;
            uint32_t a[3][4], b4[2][4];
            #pragma unroll
            for (int mt = 0; mt < 3; ++mt)
                ldsm_x4(a[mt], aBase + aplane + sw128(lutv[mt] + tapOff + kb + aKoff));
            ldsm_x4(b4[0], wb + sw128(bRow4 + kb));
            ldsm_x4(b4[1], wb + sw128(bRow4 + kb + 2048));
            #pragma unroll
            for (int mt = 0; mt < 3; ++mt)
                #pragma unroll
                for (int p2 = 0; p2 < 2; ++p2)
                    #pragma unroll
                    for (int q = 0; q < 2; ++q)
                        mma16816(acc[mt][2 * p2 + q], a[mt], b4[p2] + 2 * q);
        }
        if (s < 17) CP_WAIT0();
        __syncthreads();
    }

    // epilogue: hi/lo split via smem, coalesced stores
    const float tw = tri_w[t * 3 + 2], inv_tw = 1.f / tw;
    const float cb = crelu_b[t * 3 + 2];
    __half2* sOut = (__half2*)sm;    // [128][144] half2 = 73728 B

    #pragma unroll
    for (int mt = 0; mt < 3; ++mt)
        #pragma unroll
        for (int nt = 0; nt < 4; ++nt)
            #pragma unroll
            for (int e = 0; e < 4; ++e) {
                int p = pBase + mt * 16 + (lane >> 2) + (e >= 2 ? 8 : 0);
                int oc = nBase + nt * 8 + 2 * (lane & 3) + (e & 1);
                float d = fmaxf(xsqS3[p] - 2.f * acc[mt][nt][e] + wsqS[oc], 0.f);
                float v = 1.f - fminf(d, tw) * inv_tw;
                v = (v >= cb) ? v : 0.f;
                __half hi = __float2half(v);
                __half lo = __float2half(v - __half2float(hi));
                sOut[oc * 144 + p] = __halves2half2(hi, lo);
            }
    __syncthreads();
    size_t base = (size_t)b * 110592 + t * 36864 + half * 18432;
    for (int idx = tid; idx < 18432; idx += 384) {
        __half2 hv = sOut[idx];
        g_a3h[base + idx] = __low2half(hv);
        g_a3l[base + idx] = __high2half(hv);
    }
}

// ---------------- FC: fp16 mma, 3-pass hi/lo, double-buffered cp.async -------
#define FC_AH 0
#define FC_AL 8192
#define FC_WH 16384
#define FC_WL 23040
#define FC_BUF 29696
#define FC_DYN 59392

__global__ void __launch_bounds__(256) k_fc_mma() {
    extern __shared__ __align__(1024) unsigned char smc[];
    const int blk = blockIdx.x, tid = threadIdx.x, wid = tid >> 5, lane = tid & 31;
    const int k0 = blk * FC_SLAB_K;
    const uint32_t smB = smem_u32(smc);

    // zero-init W rows 100..103 (never re-written; cp.async only stages r<100)
    {
        uint4 z = {0u, 0u, 0u, 0u};
        for (int idx = tid; idx < 32; idx += 256) {
            int bsel = idx >> 4, r = 100 + ((idx >> 2) & 3), c = idx & 3;
            uint32_t sw = sw128((uint32_t)(r * 64 + c * 16));
            *(uint4*)(smc + bsel * FC_BUF + FC_WH + sw) = z;
            *(uint4*)(smc + bsel * FC_BUF + FC_WL + sw) = z;
        }
    }

    float acc[13][4];
    #pragma unroll
    for (int nt = 0; nt < 13; ++nt)
        #pragma unroll
        for (int e = 0; e < 4; ++e) acc[nt][e] = 0.f;

    const int mBase = wid * 16;
    const uint32_t aRow = (uint32_t)(mBase + (lane & 7) + ((lane >> 3) & 1) * 8);
    const uint32_t aK16 = ((lane >> 4) & 1) * 16;
    const uint32_t bK16 = ((lane >> 3) & 1) * 16;
    const uint32_t bRowSel = ((lane >> 4) & 1) * 8 + (lane & 7);

    // prologue: stage chunk 0 into buffer 0
    {
        int kb = k0;
        uint32_t base = smB;
        for (int idx = tid; idx < 512; idx += 256) {
            int r = idx >> 2, c = idx & 3;
            uint32_t sw = sw128((uint32_t)(r * 64 + c * 16));
            cp16(base + FC_AH + sw, g_a3h + (size_t)r * 110592 + kb + c * 8);
            cp16(base + FC_AL + sw, g_a3l + (size_t)r * 110592 + kb + c * 8);
        }
        for (int idx = tid; idx < 400; idx += 256) {
            int r = idx >> 2, c = idx & 3;
            uint32_t sw = sw128((uint32_t)(r * 64 + c * 16));
            cp16(base + FC_WH + sw, g_fwh + (size_t)r * 110592 + kb + c * 8);
            cp16(base + FC_WL + sw, g_fwl + (size_t)r * 110592 + kb + c * 8);
        }
        CP_COMMIT();
        CP_WAIT0();
    }
    __syncthreads();

    for (int ch = 0; ch < 16; ++ch) {
        if (ch < 15) {   // prefetch next chunk into other buffer
            int kb = k0 + (ch + 1) * 32;
            uint32_t base = smB + ((ch + 1) & 1) * FC_BUF;
            for (int idx = tid; idx < 512; idx += 256) {
                int r = idx >> 2, c = idx & 3;
                uint32_t sw = sw128((uint32_t)(r * 64 + c * 16));
                cp16(base + FC_AH + sw, g_a3h + (size_t)r * 110592 + kb + c * 8);
                cp16(base + FC_AL + sw, g_a3l + (size_t)r * 110592 + kb + c * 8);
            }
            for (int idx = tid; idx < 400; idx += 256) {
                int r = idx >> 2, c = idx & 3;
                uint32_t sw = sw128((uint32_t)(r * 64 + c * 16));
                cp16(base + FC_WH + sw, g_fwh + (size_t)r * 110592 + kb + c * 8);
                cp16(base + FC_WL + sw, g_fwl + (size_t)r * 110592 + kb + c * 8);
            }
            CP_COMMIT();
        }
        const uint32_t base = smB + (ch & 1) * FC_BUF;
        const uint32_t aH = base + FC_AH, aL = base + FC_AL;
        const uint32_t wH = base + FC_WH, wL = base + FC_WL;

        #pragma unroll
        for (int ks = 0; ks < 2; ++ks) {
            uint32_t ah[4], al[4];
            uint32_t ao = sw128(aRow * 64 + ks * 32 + aK16);
            ldsm_x4(ah, aH + ao);
            ldsm_x4(al, aL + ao);
            #pragma unroll
            for (int np = 0; np < 6; ++np) {
                uint32_t brow = np * 16 + bRowSel;
                uint32_t bo = sw128(brow * 64 + ks * 32 + bK16);
                uint32_t th[4], tl[4];
                ldsm_x4(th, wH + bo);
                ldsm_x4(tl, wL + bo);
                mma16816(acc[2 * np],     ah, th);
                mma16816(acc[2 * np],     ah, tl);
                mma16816(acc[2 * np],     al, th);
                mma16816(acc[2 * np + 1], ah, th + 2);
                mma16816(acc[2 * np + 1], ah, tl + 2);
                mma16816(acc[2 * np + 1], al, th + 2);
            }
            {   // tail rows 96..103 only (x2: lanes 0-15 supply addresses)
                uint32_t brow = 96 + (lane & 7);
                uint32_t bo = sw128(brow * 64 + ks * 32 + bK16);
                uint32_t bh2[2], bl2[2];
                ldsm_x2(bh2, wH + bo);
                ldsm_x2(bl2, wL + bo);
                mma16816(acc[12], ah, bh2);
                mma16816(acc[12], ah, bl2);
                mma16816(acc[12], al, bh2);
            }
        }
        if (ch < 15) CP_WAIT0();
        __syncthreads();
    }

    float* dst = g_part + (size_t)blk * 12800;
    #pragma unroll
    for (int nt = 0; nt < 13; ++nt)
        #pragma unroll
        for (int e = 0; e < 4; ++e) {
            int n = nt * 8 + 2 * (lane & 3) + (e & 1);
            if (n < 100) {
                int m = mBase + (lane >> 2) + (e >= 2 ? 8 : 0);
                dst[m * 100 + n] = acc[nt][e];
            }
        }
}

__global__ void k_fc_reduce(const float* __restrict__ fcb, float* __restrict__ out) {
    int idx = blockIdx.x * blockDim.x + threadIdx.x;
    if (idx >= NB * 100) return;
    int n = idx % 100;
    float s0 = fcb[n], s1 = 0.f, s2 = 0.f, s3 = 0.f;
    #pragma unroll 4
    for (int sb = 0; sb < FC_SLABS; sb += 4) {
        s0 += g_part[(sb + 0) * 12800 + idx];
        s1 += g_part[(sb + 1) * 12800 + idx];
        s2 += g_part[(sb + 2) * 12800 + idx];
        s3 += g_part[(sb + 3) * 12800 + idx];
    }
    out[idx] = (s0 + s1) + (s2 + s3);
}

// ---------------------------------------------------------------------------
extern "C" void kernel_launch(void* const* d_in, const int* in_sizes, int n_in,
                              void* d_out, int out_size) {
    const float* x         = (const float*)d_in[0];
    const float* W1        = (const float*)d_in[1];
    const float* W2        = (const float*)d_in[2];
    const float* W3        = (const float*)d_in[3];
    const float* tri_w     = (const float*)d_in[4];
    const float* crelu_b   = (const float*)d_in[5];
    const float* sfm_alpha = (const float*)d_in[6];
    const float* fcw       = (const float*)d_in[7];
    const float* fcb       = (const float*)d_in[8];
    float* out = (float*)d_out;

    static int attr_done = 0;
    if (!attr_done) {
        cudaFuncSetAttribute(k_conv2, cudaFuncAttributeMaxDynamicSharedMemorySize, C2_DYN);
        cudaFuncSetAttribute(k_conv3, cudaFuncAttributeMaxDynamicSharedMemorySize, C3_DYN);
        cudaFuncSetAttribute(k_fc_mma, cudaFuncAttributeMaxDynamicSharedMemorySize, FC_DYN);
        attr_done = 1;
    }

    k_prep<<<15120, 256>>>(W2, W3, fcw);
    k_wsq<<<144, 256>>>(W2, W3);
    k_layer1<<<dim3(NBT, 2), 256>>>(x, W1, tri_w, crelu_b, sfm_alpha);
    k_conv2<<<dim3(NBT, 3), 512, C2_DYN>>>(tri_w, crelu_b, sfm_alpha);
    k_conv3<<<dim3(NBT, 2), 384, C3_DYN>>>(tri_w, crelu_b);
    k_fc_mma<<<FC_SLABS, 256, FC_DYN>>>();
    k_fc_reduce<<<(NB * 100 + 255) / 256, 256>>>(fcb, out);
}

// round 9
// speedup vs baseline: 5.6765x; 1.0353x over previous
#include <cuda_runtime.h>
#include <cuda_fp16.h>
#include <cstdint>

#define NB 128
#define NT 3
#define NBT (NB*NT)

// ---------------- scratch (zero-init at load; padding never written) -------
__device__ __align__(16) __half g_a1f[NBT * 832 * 64];    // padded 26x32, ch-last
__device__ __align__(16) __half g_a2f[NBT * 224 * 128];   // padded 14x16, ch-last
__device__ __align__(16) __half g_a3h[NB * 110592];
__device__ __align__(16) __half g_a3l[NB * 110592];
__device__ __align__(16) __half g_fwh[100 * 110592];
__device__ __align__(16) __half g_fwl[100 * 110592];
__device__ float g_wsq2[NT * 128];
__device__ float g_wsq3[NT * 256];
__device__ __align__(16) __half g_w2f[27 * 8192];
__device__ __align__(16) __half g_w3f[54 * 16384];

#define FC_SLABS 216
#define FC_SLAB_K 512
__device__ float g_part[FC_SLABS * NB * 100];

// ---------------- helpers ----------------
static __device__ __forceinline__ uint32_t smem_u32(const void* p) {
    uint32_t a;
    asm("{ .reg .u64 t; cvta.to.shared.u64 t, %1; cvt.u32.u64 %0, t; }" : "=r"(a) : "l"(p));
    return a;
}
static __device__ __forceinline__ uint32_t sw128(uint32_t off) {
    return off ^ ((off >> 3) & 0x70);
}
static __device__ __forceinline__ void cp16(uint32_t dst, const void* src) {
    asm volatile("cp.async.cg.shared.global [%0], [%1], 16;" :: "r"(dst), "l"(src) : "memory");
}
#define CP_COMMIT() asm volatile("cp.async.commit_group;" ::: "memory")
#define CP_WAIT0()  asm volatile("cp.async.wait_group 0;" ::: "memory")
static __device__ __forceinline__ void ldsm_x4(uint32_t* r, uint32_t addr) {
    asm volatile("ldmatrix.sync.aligned.m8n8.x4.shared.b16 {%0,%1,%2,%3}, [%4];"
                 : "=r"(r[0]), "=r"(r[1]), "=r"(r[2]), "=r"(r[3]) : "r"(addr));
}
static __device__ __forceinline__ void ldsm_x2(uint32_t* r, uint32_t addr) {
    asm volatile("ldmatrix.sync.aligned.m8n8.x2.shared.b16 {%0,%1}, [%2];"
                 : "=r"(r[0]), "=r"(r[1]) : "r"(addr));
}
static __device__ __forceinline__ void mma16816(float* d, const uint32_t* a, const uint32_t* b) {
    asm volatile("mma.sync.aligned.m16n8k16.row.col.f32.f16.f16.f32 "
                 "{%0,%1,%2,%3}, {%4,%5,%6,%7}, {%8,%9}, {%0,%1,%2,%3};"
                 : "+f"(d[0]), "+f"(d[1]), "+f"(d[2]), "+f"(d[3])
                 : "r"(a[0]), "r"(a[1]), "r"(a[2]), "r"(a[3]), "r"(b[0]), "r"(b[1]));
}

// ---------------- prep: swizzled weight images + fc hi/lo split ----------------
__global__ void k_prep(const float* __restrict__ W2, const float* __restrict__ W3,
                       const float* __restrict__ fcw) {
    int e = blockIdx.x * blockDim.x + threadIdx.x;
    if (e < 221184) {                         // t, tap, oc(128), k(64)
        int k = e & 63, oc = (e >> 6) & 127;
        int tap = (e >> 13) % 9, t = e / (9 * 8192);
        float w = W2[(t * 128 + oc) * 576 + k * 9 + tap];
        uint32_t sw = sw128((uint32_t)(oc * 128 + k * 2));
        *(__half*)((char*)(g_w2f + (size_t)(t * 9 + tap) * 8192) + sw) = __float2half(w);
    } else if (e < 1105920) {                 // t, half, tap, oc(128), k(128)
        int e2 = e - 221184;
        int k = e2 & 127, oc = (e2 >> 7) & 127;
        int tap = (e2 >> 14) % 9, th = e2 / (9 * 16384);
        int t = th >> 1, half = th & 1;
        float w = W3[(t * 256 + half * 128 + oc) * 1152 + k * 9 + tap];
        uint32_t off = (uint32_t)((k >> 6) * 16384) + sw128((uint32_t)(oc * 128 + (k & 63) * 2));
        *(__half*)((char*)(g_w3f + (size_t)(th * 9 + tap) * 16384) + off) = __float2half(w);
    } else if (e < 1105920 + 2764800) {       // fc weight hi/lo split (4/thread)
        int e2 = e - 1105920;
        float4 w = ((const float4*)fcw)[e2];
        __half h0 = __float2half(w.x), h1 = __float2half(w.y);
        __half h2 = __float2half(w.z), h3 = __float2half(w.w);
        __half l0 = __float2half(w.x - __half2float(h0));
        __half l1 = __float2half(w.y - __half2float(h1));
        __half l2 = __float2half(w.z - __half2float(h2));
        __half l3 = __float2half(w.w - __half2float(h3));
        ((__half2*)g_fwh)[e2 * 2]     = __halves2half2(h0, h1);
        ((__half2*)g_fwh)[e2 * 2 + 1] = __halves2half2(h2, h3);
        ((__half2*)g_fwl)[e2 * 2]     = __halves2half2(l0, l1);
        ((__half2*)g_fwl)[e2 * 2 + 1] = __halves2half2(l2, l3);
    }
}

// wsq: one warp per output channel, shfl reduce
__global__ void __launch_bounds__(256) k_wsq(const float* __restrict__ W2,
                                             const float* __restrict__ W3) {
    int oid = blockIdx.x * 8 + (threadIdx.x >> 5);
    int lane = threadIdx.x & 31;
    float s = 0.f;
    if (oid < NT * 128) {
        const float* p = W2 + oid * 576;
        for (int k = lane; k < 576; k += 32) {
            float w = __half2float(__float2half(p[k])); s += w * w;
        }
    } else {
        const float* p = W3 + (oid - NT * 128) * 1152;
        for (int k = lane; k < 1152; k += 32) {
            float w = __half2float(__float2half(p[k])); s += w * w;
        }
    }
    #pragma unroll
    for (int d = 16; d > 0; d >>= 1) s += __shfl_xor_sync(0xffffffffu, s, d);
    if (lane == 0) {
        if (oid < NT * 128) g_wsq2[oid] = s;
        else g_wsq3[oid - NT * 128] = s;
    }
}

// ---------------- layer 1: fp32 SIMT, y-split, 2 pooled outputs/iter ----------
__global__ void __launch_bounds__(256) k_layer1(
    const float* __restrict__ x, const float* __restrict__ W1,
    const float* __restrict__ tri_w, const float* __restrict__ crelu_b,
    const float* __restrict__ sfm_alpha)
{
    __shared__ __align__(16) float xpadL[28 * 52];
    __shared__ float xsqL[24 * 48];
    __shared__ float w1s[64 * 25];
    __shared__ float wsq1s[64];

    const int bt = blockIdx.x, t = bt % NT, h = blockIdx.y, tid = threadIdx.x;

    for (int idx = tid; idx < 28 * 52; idx += 256) {
        int r = idx / 52, c = idx % 52;
        int gr = h * 24 + r - 2, gc = c - 2;
        xpadL[idx] = (gr >= 0 && gr < 48 && gc >= 0 && gc < 48)
                   ? x[bt * 2304 + gr * 48 + gc] : 0.f;
    }
    for (int idx = tid; idx < 1600; idx += 256) w1s[idx] = W1[t * 1600 + idx];
    __syncthreads();

    if (tid < 64) {
        float s = 0.f;
        #pragma unroll
        for (int k = 0; k < 25; ++k) { float w = w1s[tid * 25 + k]; s += w * w; }
        wsq1s[tid] = s;
    }
    for (int idx = tid; idx < 24 * 48; idx += 256) {
        int y = idx / 48, xx = idx % 48;
        float s = 0.f;
        #pragma unroll
        for (int ky = 0; ky < 5; ++ky)
            #pragma unroll
            for (int kx = 0; kx < 5; ++kx) {
                float v = xpadL[(y + ky) * 52 + xx + kx];
                s += v * v;
            }
        xsqL[idx] = s;
    }
    __syncthreads();

    const int o = tid >> 2, sub = tid & 3;
    float wr[25];
    #pragma unroll
    for (int k = 0; k < 25; ++k) wr[k] = w1s[o * 25 + k];
    const float wq = wsq1s[o];
    const float tw = tri_w[t * 3 + 0], inv_tw = 1.f / tw;
    const float cb = crelu_b[t * 3 + 0];
    const float al = sfm_alpha[t * 2 + 0];
    const float c00 = al * al * al * 0.25f, c01 = al * al * 0.25f;
    const float c10 = al * 0.25f, c11 = 0.25f;

    for (int it = 0; it < 36; ++it) {
        int p = it * 4 + sub;
        int pi = p / 12, pj = (p % 12) * 2;
        float pt[6][8];
        #pragma unroll
        for (int r = 0; r < 6; ++r) {
            const float* row = &xpadL[(2 * pi + r) * 52 + 2 * pj];
            #pragma unroll
            for (int s2 = 0; s2 < 4; ++s2) {
                float2 u = *(const float2*)(row + 2 * s2);
                pt[r][2 * s2] = u.x; pt[r][2 * s2 + 1] = u.y;
            }
        }
        float vv[2][4];
        #pragma unroll
        for (int a = 0; a < 2; ++a)
            #pragma unroll
            for (int b2 = 0; b2 < 4; ++b2) {
                float cr = 0.f;
                #pragma unroll
                for (int ky = 0; ky < 5; ++ky)
                    #pragma unroll
                    for (int kx = 0; kx < 5; ++kx)
                        cr += wr[ky * 5 + kx] * pt[a + ky][b2 + kx];
                float d = xsqL[(2 * pi + a) * 48 + 2 * pj + b2] - 2.f * cr + wq;
                d = fmaxf(d, 0.f);
                float v = 1.f - fminf(d, tw) * inv_tw;
                vv[a][b2] = (v >= cb) ? v : 0.f;
            }
        float pool0 = c00 * vv[0][0] + c01 * vv[0][1] + c10 * vv[1][0] + c11 * vv[1][1];
        float pool1 = c00 * vv[0][2] + c01 * vv[0][3] + c10 * vv[1][2] + c11 * vv[1][3];
        int gi = h * 12 + pi;
        size_t cell = ((size_t)bt * 832 + (gi + 1) * 32 + (pj + 1)) * 64 + o;
        g_a1f[cell] = __float2half(pool0);
        g_a1f[cell + 64] = __float2half(pool1);
    }
}

// ---------------- conv2: implicit GEMM, 256thr/M=96 blocks (3/SM) -----------
#define C2_AB 24576
#define C2_DYN 57344

__global__ void __launch_bounds__(256) k_conv2(
    const float* __restrict__ tri_w, const float* __restrict__ crelu_b,
    const float* __restrict__ sfm_alpha)
{
    extern __shared__ __align__(1024) unsigned char sm[];
    __shared__ uint32_t lutS[96];
    __shared__ float xsqS[96];
    __shared__ float wsqS[128];
    __shared__ float cellsq[192];

    const int bt = blockIdx.x, t = bt % NT, ytile = blockIdx.y;
    const int y0 = ytile * 4;                 // 4 conv rows per block
    const int tid = threadIdx.x, wid = tid >> 5, lane = tid & 31;
    const uint32_t aBase = smem_u32(sm);
    const uint32_t wBase = aBase + C2_AB;

    {   // stage A: padded rows y0..y0+5 (192 cells)
        const uint4* src = (const uint4*)(g_a1f + ((size_t)bt * 832 + y0 * 32) * 64);
        #pragma unroll
        for (int u = 0; u < 6; ++u) {
            int idx = tid + u * 256;
            uint32_t off = sw128((uint32_t)((idx >> 3) * 128 + (idx & 7) * 16));
            *(uint4*)(sm + off) = src[idx];
        }
    }
    {   // stage W tap 0 into buf 0
        const uint4* wsrc = (const uint4*)(g_w2f + (size_t)(t * 9) * 8192);
        uint4* wdst = (uint4*)(sm + C2_AB);
        #pragma unroll
        for (int u = 0; u < 4; ++u) wdst[tid + u * 256] = wsrc[tid + u * 256];
    }
    if (tid < 96) {
        int r = tid / 24, c = tid % 24;
        lutS[tid] = (uint32_t)((r * 32 + c) * 128);
    }
    if (tid < 128) wsqS[tid] = g_wsq2[t * 128 + tid];
    __syncthreads();

    // fused xsq: per-cell channel sumsq (swizzle-invariant row sum)
    if (tid < 192) {
        float s = 0.f;
        #pragma unroll
        for (int ch = 0; ch < 8; ++ch) {
            uint4 v = *(const uint4*)(sm + sw128((uint32_t)(tid * 128 + ch * 16)));
            const __half2* hh = (const __half2*)&v;
            #pragma unroll
            for (int q = 0; q < 4; ++q) {
                float2 f = __half22float2(hh[q]);
                s += f.x * f.x + f.y * f.y;
            }
        }
        cellsq[tid] = s;
    }
    uint32_t lutv[3];
    const int wm = wid >> 2, wn = wid & 3;    // wm 0..1, wn 0..3
    const int pBase = wm * 48, nBase = wn * 32;
    #pragma unroll
    for (int mt = 0; mt < 3; ++mt)
        lutv[mt] = lutS[pBase + mt * 16 + (lane & 7) + ((lane >> 3) & 1) * 8];
    __syncthreads();
    if (tid < 96) {
        int r = tid / 24, c = tid % 24;
        float s = 0.f;
        #pragma unroll
        for (int dr = 0; dr < 3; ++dr)
            #pragma unroll
            for (int dc = 0; dc < 3; ++dc)
                s += cellsq[(r + dr) * 32 + c + dc];
        xsqS[tid] = s;
    }

    const uint32_t aKoff = ((lane >> 4) & 1) * 16;
    const uint32_t bRow4 = (uint32_t)((nBase + ((lane >> 4) & 1) * 8 + (lane & 7)) * 128
                                      + ((lane >> 3) & 1) * 16);

    float acc[3][4][4];
    #pragma unroll
    for (int mt = 0; mt < 3; ++mt)
        #pragma unroll
        for (int nt = 0; nt < 4; ++nt)
            #pragma unroll
            for (int e = 0; e < 4; ++e) acc[mt][nt][e] = 0.f;

    for (int tap = 0; tap < 9; ++tap) {
        if (tap < 8) {   // cp.async prefetch next tap
            const char* wsrc = (const char*)(g_w2f + (size_t)(t * 9 + tap + 1) * 8192);
            uint32_t wdst = wBase + (((tap + 1) & 1) << 14);
            #pragma unroll
            for (int u = 0; u < 4; ++u)
                cp16(wdst + (tid + u * 256) * 16, wsrc + (tid + u * 256) * 16);
            CP_COMMIT();
        }
        const uint32_t wb = wBase + ((tap & 1) << 14);
        const uint32_t tapOff = (uint32_t)(((tap / 3) * 32 + (tap % 3)) * 128);
        #pragma unroll
        for (int ks = 0; ks < 4; ++ks) {
            const uint32_t kb = ks * 32;
            uint32_t a[3][4], b4[2][4];
            #pragma unroll
            for (int mt = 0; mt < 3; ++mt)
                ldsm_x4(a[mt], aBase + sw128(lutv[mt] + tapOff + kb + aKoff));
            ldsm_x4(b4[0], wb + sw128(bRow4 + kb));
            ldsm_x4(b4[1], wb + sw128(bRow4 + kb + 2048));
            #pragma unroll
            for (int mt = 0; mt < 3; ++mt)
                #pragma unroll
                for (int p2 = 0; p2 < 2; ++p2)
                    #pragma unroll
                    for (int q = 0; q < 2; ++q)
                        mma16816(acc[mt][2 * p2 + q], a[mt], b4[p2] + 2 * q);
        }
        if (tap < 8) CP_WAIT0();
        __syncthreads();
    }

    const float tw = tri_w[t * 3 + 1], inv_tw = 1.f / tw;
    const float cb = crelu_b[t * 3 + 1];
    const float al = sfm_alpha[t * 2 + 1];
    const float c00 = al * al * al * 0.25f, c01 = al * al * 0.25f;
    const float c10 = al * 0.25f, c11 = 0.25f;
    float* vbuf = (float*)sm;   // [96][130] = 49920 B

    #pragma unroll
    for (int mt = 0; mt < 3; ++mt)
        #pragma unroll
        for (int nt = 0; nt < 4; ++nt)
            #pragma unroll
            for (int e = 0; e < 4; ++e) {
                int p = pBase + mt * 16 + (lane >> 2) + (e >= 2 ? 8 : 0);
                int oc = nBase + nt * 8 + 2 * (lane & 3) + (e & 1);
                float d = fmaxf(xsqS[p] - 2.f * acc[mt][nt][e] + wsqS[oc], 0.f);
                float v = 1.f - fminf(d, tw) * inv_tw;
                vbuf[p * 130 + oc] = (v >= cb) ? v : 0.f;
            }
    __syncthreads();

    #pragma unroll
    for (int u = 0; u < 12; ++u) {
        int idx = tid + u * 256;
        int oc = idx & 127, q = idx >> 7;       // q: 0..23
        int pr = q / 12, pc = q % 12;
        int p00 = (2 * pr) * 24 + 2 * pc;
        float pooled = c00 * vbuf[p00 * 130 + oc] + c01 * vbuf[(p00 + 1) * 130 + oc]
                     + c10 * vbuf[(p00 + 24) * 130 + oc] + c11 * vbuf[(p00 + 25) * 130 + oc];
        int gi = ytile * 2 + pr;
        g_a2f[((size_t)bt * 224 + (gi + 1) * 16 + (pc + 1)) * 128 + oc] = __float2half(pooled);
    }
}

// ---------------- conv3: implicit GEMM, fused xsq, cp.async W prefetch -------
#define C3_AP 28672
#define C3_WB 57344
#define C3_DYN 90112

__global__ void __launch_bounds__(384) k_conv3(
    const float* __restrict__ tri_w, const float* __restrict__ crelu_b)
{
    extern __shared__ __align__(1024) unsigned char sm[];
    __shared__ uint32_t lutS[144];
    __shared__ float xsqS3[144];
    __shared__ float wsqS[128];
    __shared__ float cellsq3[224];

    const int bt = blockIdx.x, t = bt % NT, b = bt / NT;
    const int half = blockIdx.y;
    const int tid = threadIdx.x, wid = tid >> 5, lane = tid & 31;
    const uint32_t aBase = smem_u32(sm);
    const uint32_t wBase = aBase + C3_WB;
    const uint4* wImg = (const uint4*)g_w3f + (size_t)((t * 2 + half) * 9) * 2048;

    {   // stage A: 224 cells x 256B, 2 k-planes
        const uint4* src = (const uint4*)(g_a2f + (size_t)bt * 224 * 128);
        for (int idx = tid; idx < 3584; idx += 384) {
            int cell = idx >> 4, chunk = idx & 15;
            uint32_t off = (uint32_t)((chunk >> 3) * C3_AP)
                         + sw128((uint32_t)(cell * 128 + (chunk & 7) * 16));
            *(uint4*)(sm + off) = src[idx];
        }
    }
    {   // stage W step 0
        uint4* wdst = (uint4*)(sm + C3_WB);
        for (int i = tid; i < 1024; i += 384) wdst[i] = wImg[i];
    }
    if (tid < 144) {
        int r = tid / 12, c = tid % 12;
        lutS[tid] = (uint32_t)((r * 16 + c) * 128);
    }
    if (tid < 128) wsqS[tid] = g_wsq3[t * 256 + half * 128 + tid];
    __syncthreads();

    // fused xsq3
    if (tid < 224) {
        float s = 0.f;
        #pragma unroll
        for (int pl = 0; pl < 2; ++pl)
            #pragma unroll
            for (int ch = 0; ch < 8; ++ch) {
                uint4 v = *(const uint4*)(sm + pl * C3_AP
                                          + sw128((uint32_t)(tid * 128 + ch * 16)));
                const __half2* hh = (const __half2*)&v;
                #pragma unroll
                for (int q = 0; q < 4; ++q) {
                    float2 f = __half22float2(hh[q]);
                    s += f.x * f.x + f.y * f.y;
                }
            }
        cellsq3[tid] = s;
    }
    uint32_t lutv[3];
    const int wm = wid >> 2, wn = wid & 3;
    const int pBase = wm * 48, nBase = wn * 32;
    #pragma unroll
    for (int mt = 0; mt < 3; ++mt)
        lutv[mt] = lutS[pBase + mt * 16 + (lane & 7) + ((lane >> 3) & 1) * 8];
    __syncthreads();
    if (tid < 144) {
        int r = tid / 12, c = tid % 12;
        float s = 0.f;
        #pragma unroll
        for (int dr = 0; dr < 3; ++dr)
            #pragma unroll
            for (int dc = 0; dc < 3; ++dc)
                s += cellsq3[(r + dr) * 16 + c + dc];
        xsqS3[tid] = s;
    }

    const uint32_t aKoff = ((lane >> 4) & 1) * 16;
    const uint32_t bRow4 = (uint32_t)((nBase + ((lane >> 4) & 1) * 8 + (lane & 7)) * 128
                                      + ((lane >> 3) & 1) * 16);

    float acc[3][4][4];
    #pragma unroll
    for (int mt = 0; mt < 3; ++mt)
        #pragma unroll
        for (int nt = 0; nt < 4; ++nt)
            #pragma unroll
            for (int e = 0; e < 4; ++e) acc[mt][nt][e] = 0.f;

    for (int s = 0; s < 18; ++s) {             // (tap, plane) steps
        if (s < 17) {                          // cp.async prefetch next step
            int s1 = s + 1;
            const char* wsrc = (const char*)(wImg + (s1 >> 1) * 2048 + (s1 & 1) * 1024);
            uint32_t wdst = wBase + ((s1 & 1) << 14);
            for (int i = tid; i < 1024; i += 384)
                cp16(wdst + i * 16, wsrc + i * 16);
            CP_COMMIT();
        }
        const int tap = s >> 1, pl = s & 1;
        const uint32_t aplane = pl ? (uint32_t)C3_AP : 0u;
        const uint32_t wb = wBase + ((s & 1) << 14);
        const uint32_t tapOff = (uint32_t)(((tap / 3) * 16 + (tap % 3)) * 128);
        #pragma unroll
        for (int ks = 0; ks < 4; ++ks) {
            const uint32_t kb = ks * 32;
            uint32_t a[3][4], b4[2][4];
            #pragma unroll
            for (int mt = 0; mt < 3; ++mt)
                ldsm_x4(a[mt], aBase + aplane + sw128(lutv[mt] + tapOff + kb + aKoff));
            ldsm_x4(b4[0], wb + sw128(bRow4 + kb));
            ldsm_x4(b4[1], wb + sw128(bRow4 + kb + 2048));
            #pragma unroll
            for (int mt = 0; mt < 3; ++mt)
                #pragma unroll
                for (int p2 = 0; p2 < 2; ++p2)
                    #pragma unroll
                    for (int q = 0; q < 2; ++q)
                        mma16816(acc[mt][2 * p2 + q], a[mt], b4[p2] + 2 * q);
        }
        if (s < 17) CP_WAIT0();
        __syncthreads();
    }

    // epilogue: hi/lo split via smem, coalesced stores
    const float tw = tri_w[t * 3 + 2], inv_tw = 1.f / tw;
    const float cb = crelu_b[t * 3 + 2];
    __half2* sOut = (__half2*)sm;    // [128][144] half2 = 73728 B

    #pragma unroll
    for (int mt = 0; mt < 3; ++mt)
        #pragma unroll
        for (int nt = 0; nt < 4; ++nt)
            #pragma unroll
            for (int e = 0; e < 4; ++e) {
                int p = pBase + mt * 16 + (lane >> 2) + (e >= 2 ? 8 : 0);
                int oc = nBase + nt * 8 + 2 * (lane & 3) + (e & 1);
                float d = fmaxf(xsqS3[p] - 2.f * acc[mt][nt][e] + wsqS[oc], 0.f);
                float v = 1.f - fminf(d, tw) * inv_tw;
                v = (v >= cb) ? v : 0.f;
                __half hi = __float2half(v);
                __half lo = __float2half(v - __half2float(hi));
                sOut[oc * 144 + p] = __halves2half2(hi, lo);
            }
    __syncthreads();
    size_t base = (size_t)b * 110592 + t * 36864 + half * 18432;
    for (int idx = tid; idx < 18432; idx += 384) {
        __half2 hv = sOut[idx];
        g_a3h[base + idx] = __low2half(hv);
        g_a3l[base + idx] = __high2half(hv);
    }
}

// ---------------- FC: fp16 mma, 3-pass hi/lo, double-buffered cp.async -------
#define FC_AH 0
#define FC_AL 8192
#define FC_WH 16384
#define FC_WL 23040
#define FC_BUF 29696
#define FC_DYN 59392

__global__ void __launch_bounds__(256) k_fc_mma() {
    extern __shared__ __align__(1024) unsigned char smc[];
    const int blk = blockIdx.x, tid = threadIdx.x, wid = tid >> 5, lane = tid & 31;
    const int k0 = blk * FC_SLAB_K;
    const uint32_t smB = smem_u32(smc);

    // zero-init W rows 100..103 (never re-written; cp.async only stages r<100)
    {
        uint4 z = {0u, 0u, 0u, 0u};
        for (int idx = tid; idx < 32; idx += 256) {
            int bsel = idx >> 4, r = 100 + ((idx >> 2) & 3), c = idx & 3;
            uint32_t sw = sw128((uint32_t)(r * 64 + c * 16));
            *(uint4*)(smc + bsel * FC_BUF + FC_WH + sw) = z;
            *(uint4*)(smc + bsel * FC_BUF + FC_WL + sw) = z;
        }
    }

    float acc[13][4];
    #pragma unroll
    for (int nt = 0; nt < 13; ++nt)
        #pragma unroll
        for (int e = 0; e < 4; ++e) acc[nt][e] = 0.f;

    const int mBase = wid * 16;
    const uint32_t aRow = (uint32_t)(mBase + (lane & 7) + ((lane >> 3) & 1) * 8);
    const uint32_t aK16 = ((lane >> 4) & 1) * 16;
    const uint32_t bK16 = ((lane >> 3) & 1) * 16;
    const uint32_t bRowSel = ((lane >> 4) & 1) * 8 + (lane & 7);

    // prologue: stage chunk 0 into buffer 0
    {
        int kb = k0;
        uint32_t base = smB;
        for (int idx = tid; idx < 512; idx += 256) {
            int r = idx >> 2, c = idx & 3;
            uint32_t sw = sw128((uint32_t)(r * 64 + c * 16));
            cp16(base + FC_AH + sw, g_a3h + (size_t)r * 110592 + kb + c * 8);
            cp16(base + FC_AL + sw, g_a3l + (size_t)r * 110592 + kb + c * 8);
        }
        for (int idx = tid; idx < 400; idx += 256) {
            int r = idx >> 2, c = idx & 3;
            uint32_t sw = sw128((uint32_t)(r * 64 + c * 16));
            cp16(base + FC_WH + sw, g_fwh + (size_t)r * 110592 + kb + c * 8);
            cp16(base + FC_WL + sw, g_fwl + (size_t)r * 110592 + kb + c * 8);
        }
        CP_COMMIT();
        CP_WAIT0();
    }
    __syncthreads();

    for (int ch = 0; ch < 16; ++ch) {
        if (ch < 15) {   // prefetch next chunk into other buffer
            int kb = k0 + (ch + 1) * 32;
            uint32_t base = smB + ((ch + 1) & 1) * FC_BUF;
            for (int idx = tid; idx < 512; idx += 256) {
                int r = idx >> 2, c = idx & 3;
                uint32_t sw = sw128((uint32_t)(r * 64 + c * 16));
                cp16(base + FC_AH + sw, g_a3h + (size_t)r * 110592 + kb + c * 8);
                cp16(base + FC_AL + sw, g_a3l + (size_t)r * 110592 + kb + c * 8);
            }
            for (int idx = tid; idx < 400; idx += 256) {
                int r = idx >> 2, c = idx & 3;
                uint32_t sw = sw128((uint32_t)(r * 64 + c * 16));
                cp16(base + FC_WH + sw, g_fwh + (size_t)r * 110592 + kb + c * 8);
                cp16(base + FC_WL + sw, g_fwl + (size_t)r * 110592 + kb + c * 8);
            }
            CP_COMMIT();
        }
        const uint32_t base = smB + (ch & 1) * FC_BUF;
        const uint32_t aH = base + FC_AH, aL = base + FC_AL;
        const uint32_t wH = base + FC_WH, wL = base + FC_WL;

        #pragma unroll
        for (int ks = 0; ks < 2; ++ks) {
            uint32_t ah[4], al[4];
            uint32_t ao = sw128(aRow * 64 + ks * 32 + aK16);
            ldsm_x4(ah, aH + ao);
            ldsm_x4(al, aL + ao);
            #pragma unroll
            for (int np = 0; np < 6; ++np) {
                uint32_t brow = np * 16 + bRowSel;
                uint32_t bo = sw128(brow * 64 + ks * 32 + bK16);
                uint32_t th[4], tl[4];
                ldsm_x4(th, wH + bo);
                ldsm_x4(tl, wL + bo);
                mma16816(acc[2 * np],     ah, th);
                mma16816(acc[2 * np],     ah, tl);
                mma16816(acc[2 * np],     al, th);
                mma16816(acc[2 * np + 1], ah, th + 2);
                mma16816(acc[2 * np + 1], ah, tl + 2);
                mma16816(acc[2 * np + 1], al, th + 2);
            }
            {   // tail rows 96..103 only (x2: lanes 0-15 supply addresses)
                uint32_t brow = 96 + (lane & 7);
                uint32_t bo = sw128(brow * 64 + ks * 32 + bK16);
                uint32_t bh2[2], bl2[2];
                ldsm_x2(bh2, wH + bo);
                ldsm_x2(bl2, wL + bo);
                mma16816(acc[12], ah, bh2);
                mma16816(acc[12], ah, bl2);
                mma16816(acc[12], al, bh2);
            }
        }
        if (ch < 15) CP_WAIT0();
        __syncthreads();
    }

    float* dst = g_part + (size_t)blk * 12800;
    #pragma unroll
    for (int nt = 0; nt < 13; ++nt)
        #pragma unroll
        for (int e = 0; e < 4; ++e) {
            int n = nt * 8 + 2 * (lane & 3) + (e & 1);
            if (n < 100) {
                int m = mBase + (lane >> 2) + (e >= 2 ? 8 : 0);
                dst[m * 100 + n] = acc[nt][e];
            }
        }
}

__global__ void k_fc_reduce(const float* __restrict__ fcb, float* __restrict__ out) {
    int idx = blockIdx.x * blockDim.x + threadIdx.x;
    if (idx >= NB * 100) return;
    int n = idx % 100;
    float s0 = fcb[n], s1 = 0.f, s2 = 0.f, s3 = 0.f;
    #pragma unroll 4
    for (int sb = 0; sb < FC_SLABS; sb += 4) {
        s0 += g_part[(sb + 0) * 12800 + idx];
        s1 += g_part[(sb + 1) * 12800 + idx];
        s2 += g_part[(sb + 2) * 12800 + idx];
        s3 += g_part[(sb + 3) * 12800 + idx];
    }
    out[idx] = (s0 + s1) + (s2 + s3);
}

// ---------------------------------------------------------------------------
extern "C" void kernel_launch(void* const* d_in, const int* in_sizes, int n_in,
                              void* d_out, int out_size) {
    const float* x         = (const float*)d_in[0];
    const float* W1        = (const float*)d_in[1];
    const float* W2        = (const float*)d_in[2];
    const float* W3        = (const float*)d_in[3];
    const float* tri_w     = (const float*)d_in[4];
    const float* crelu_b   = (const float*)d_in[5];
    const float* sfm_alpha = (const float*)d_in[6];
    const float* fcw       = (const float*)d_in[7];
    const float* fcb       = (const float*)d_in[8];
    float* out = (float*)d_out;

    static int attr_done = 0;
    if (!attr_done) {
        cudaFuncSetAttribute(k_conv2, cudaFuncAttributeMaxDynamicSharedMemorySize, C2_DYN);
        cudaFuncSetAttribute(k_conv3, cudaFuncAttributeMaxDynamicSharedMemorySize, C3_DYN);
        cudaFuncSetAttribute(k_fc_mma, cudaFuncAttributeMaxDynamicSharedMemorySize, FC_DYN);
        attr_done = 1;
    }

    k_prep<<<15120, 256>>>(W2, W3, fcw);
    k_wsq<<<144, 256>>>(W2, W3);
    k_layer1<<<dim3(NBT, 2), 256>>>(x, W1, tri_w, crelu_b, sfm_alpha);
    k_conv2<<<dim3(NBT, 6), 256, C2_DYN>>>(tri_w, crelu_b, sfm_alpha);
    k_conv3<<<dim3(NBT, 2), 384, C3_DYN>>>(tri_w, crelu_b);
    k_fc_mma<<<FC_SLABS, 256, FC_DYN>>>();
    k_fc_reduce<<<(NB * 100 + 255) / 256, 256>>>(fcb, out);
}